// round 1
// baseline (speedup 1.0000x reference)
#include <cuda_runtime.h>
#include <math.h>

#define SEQ     2048
#define HIDDEN  2048
#define HD      128
#define NH      16
#define NKV     2

// ---------------- scratch (device globals: no allocation allowed) ----------------
__device__ __align__(16) float g_q[(size_t)NH  * SEQ * HD];   // 16 MB
__device__ __align__(16) float g_k[(size_t)NKV * SEQ * HD];   // 2 MB
__device__ __align__(16) float g_v[(size_t)NKV * SEQ * HD];   // 2 MB
__device__ __align__(16) float g_s[(size_t)NH  * SEQ * SEQ];  // 256 MB
__device__ __align__(16) float g_a[(size_t)NH  * SEQ * HD];   // 16 MB

// ---------------- generic 64x64x16 register-tiled SGEMM ----------------
// C[M,N] = A[M,K] @ op(B) where op(B)=B[N,K]^T if TRANSB else B[K,N].
// Batched over blockIdx.z with per-batch strides; B batch index = z / bdiv (GQA).
// SCORES: epilogue c = c*scale + mask[gm*SEQ+gn], and fully-masked blocks skip the mainloop.
// causal!=0: cap K at m0+64 (rows in this block never need k beyond the diagonal).
template<bool TRANSB, bool SCORES>
__global__ __launch_bounds__(256)
void gemm64(const float* __restrict__ Ab, const float* __restrict__ Bb,
            float* __restrict__ Cb,
            int M, int N, int K, int lda, int ldb, int ldc,
            long sA, long sB, long sC, int bdiv,
            float scale, const float* __restrict__ mask, int causal)
{
    const int z = blockIdx.z;
    const float* A = Ab + (long)z * sA;
    const float* B = Bb + (long)(z / bdiv) * sB;
    float*       C = Cb + (long)z * sC;
    const int m0 = blockIdx.y * 64;
    const int n0 = blockIdx.x * 64;
    const int tid = threadIdx.x;
    const int ty = tid >> 4, tx = tid & 15;

    __shared__ __align__(16) float As[16][64];
    __shared__ __align__(16) float Bs[16][64];

    float acc[4][4];
#pragma unroll
    for (int i = 0; i < 4; i++)
#pragma unroll
        for (int j = 0; j < 4; j++) acc[i][j] = 0.f;

    int Keff = K;
    if (causal) { int km = m0 + 64; Keff = km < K ? km : K; }
    const bool skip = SCORES && (n0 > m0 + 63);   // block entirely above diagonal

    if (!skip) {
        const int arow = tid >> 2;            // 0..63
        const int ac4  = (tid & 3) << 2;      // 0,4,8,12
        const int bkk  = tid >> 4;            // 0..15   (NN load)
        const int bn4  = (tid & 15) << 2;     // 0..60   (NN load)

        for (int k0 = 0; k0 < Keff; k0 += 16) {
            float4 av = *(const float4*)(A + (long)(m0 + arow) * lda + k0 + ac4);
            As[ac4 + 0][arow] = av.x; As[ac4 + 1][arow] = av.y;
            As[ac4 + 2][arow] = av.z; As[ac4 + 3][arow] = av.w;
            if (TRANSB) {
                float4 bv = *(const float4*)(B + (long)(n0 + arow) * ldb + k0 + ac4);
                Bs[ac4 + 0][arow] = bv.x; Bs[ac4 + 1][arow] = bv.y;
                Bs[ac4 + 2][arow] = bv.z; Bs[ac4 + 3][arow] = bv.w;
            } else {
                float4 bv = *(const float4*)(B + (long)(k0 + bkk) * ldb + n0 + bn4);
                *(float4*)&Bs[bkk][bn4] = bv;
            }
            __syncthreads();
#pragma unroll
            for (int kk = 0; kk < 16; kk++) {
                float4 a = *(const float4*)&As[kk][ty << 2];
                float4 b = *(const float4*)&Bs[kk][tx << 2];
                float ar[4] = {a.x, a.y, a.z, a.w};
                float br[4] = {b.x, b.y, b.z, b.w};
#pragma unroll
                for (int i = 0; i < 4; i++)
#pragma unroll
                    for (int j = 0; j < 4; j++)
                        acc[i][j] = fmaf(ar[i], br[j], acc[i][j]);
            }
            __syncthreads();
        }
    }

#pragma unroll
    for (int i = 0; i < 4; i++) {
        const int gm = m0 + (ty << 2) + i;
#pragma unroll
        for (int j = 0; j < 4; j++) {
            const int gn = n0 + (tx << 2) + j;
            float c = acc[i][j];
            if (SCORES) c = c * scale + mask[(long)gm * SEQ + gn];
            C[(long)gm * ldc + gn] = c;
        }
    }
}

// ---------------- RoPE (in-place on projected q/k) ----------------
// buf: [heads, SEQ, 128]; pair (i, i+64) rotated by angle = pos[l] * theta^(-i/64).
// All-fp32 with Cody-Waite 2pi reduction (angle up to ~2047 rad) so fast-math can't hurt us.
__global__ __launch_bounds__(256)
void rope_k(float* __restrict__ buf, const int* __restrict__ pos, int heads)
{
    int idx = blockIdx.x * 256 + threadIdx.x;
    int total = heads * SEQ * 64;
    if (idx >= total) return;
    int i = idx & 63;
    int l = (idx >> 6) % SEQ;
    int n = idx / (SEQ * 64);

    // inv_freq = 1e6^(-i/64) = 2^(-i * log2(1e6)/64)
    float invf = exp2f(-(float)i * 0.31143075889569023f);
    float ang  = (float)pos[l] * invf;
    // reduce mod 2*pi: q exact (q<=326, c1 has 8 mantissa bits)
    float q  = rintf(ang * 0.15915494309189535f);
    float r  = ang - q * 6.28125f;
    r        = r   - q * 1.9353071795864769e-3f;
    float s, c;
    sincosf(r, &s, &c);

    float* p = buf + ((long)n * SEQ + l) * HD;
    float x1 = p[i], x2 = p[i + 64];
    p[i]      = x1 * c - x2 * s;
    p[i + 64] = x2 * c + x1 * s;
}

// ---------------- row softmax (in place, one block per row) ----------------
__global__ __launch_bounds__(256)
void softmax_k(float* __restrict__ sc)
{
    float* p = sc + (long)blockIdx.x * SEQ;
    const int t = threadIdx.x;
    __shared__ float red[256];

    float m = -1e30f;
    for (int j = t; j < SEQ; j += 256) m = fmaxf(m, p[j]);
    red[t] = m; __syncthreads();
    for (int st = 128; st > 0; st >>= 1) {
        if (t < st) red[t] = fmaxf(red[t], red[t + st]);
        __syncthreads();
    }
    m = red[0];
    __syncthreads();

    float sum = 0.f;
    for (int j = t; j < SEQ; j += 256) { float e = expf(p[j] - m); p[j] = e; sum += e; }
    red[t] = sum; __syncthreads();
    for (int st = 128; st > 0; st >>= 1) {
        if (t < st) red[t] += red[t + st];
        __syncthreads();
    }
    float inv = 1.f / red[0];
    for (int j = t; j < SEQ; j += 256) p[j] *= inv;
}

// ---------------- launch ----------------
extern "C" void kernel_launch(void* const* d_in, const int* in_sizes, int n_in,
                              void* d_out, int out_size)
{
    const float* qh   = (const float*)d_in[0]; // (16,1,2048,2048)
    const float* kh   = (const float*)d_in[1]; // (2,1,2048,2048)
    const float* vh   = (const float*)d_in[2]; // (2,1,2048,2048)
    const float* mask = (const float*)d_in[3]; // (1,1,2048,2048)
    const int*   pos  = (const int*)  d_in[4]; // (1,2048)
    const float* qw   = (const float*)d_in[5]; // (2048,2048)
    const float* kw   = (const float*)d_in[6]; // (256,2048)
    const float* vw   = (const float*)d_in[7]; // (256,2048)
    const float* ow   = (const float*)d_in[8]; // (2048,2048)
    float*       out  = (float*)d_out;          // (16,1,2048,2048)

    float *qb, *kb, *vb, *sb, *ab;
    cudaGetSymbolAddress((void**)&qb, g_q);
    cudaGetSymbolAddress((void**)&kb, g_k);
    cudaGetSymbolAddress((void**)&vb, g_v);
    cudaGetSymbolAddress((void**)&sb, g_s);
    cudaGetSymbolAddress((void**)&ab, g_a);

    const dim3 blk(256);
    const long HH = (long)SEQ * HIDDEN;      // 2048*2048
    const long HDW = (long)HD * HIDDEN;      // 128*2048
    const long SH  = (long)SEQ * HD;         // 2048*128
    const long SS  = (long)SEQ * SEQ;        // 2048*2048
    const float isqrt = 0.08838834764831845f; // 1/sqrt(128)

    // Q/K/V projections: C[l,h] = X[l,:] . W[h,:]   (NT)
    gemm64<true,  false><<<dim3(2, 32, NH),  blk>>>(qh, qw, qb, SEQ, HD, HIDDEN,
        HIDDEN, HIDDEN, HD, HH, HDW, SH, 1, 1.f, nullptr, 0);
    gemm64<true,  false><<<dim3(2, 32, NKV), blk>>>(kh, kw, kb, SEQ, HD, HIDDEN,
        HIDDEN, HIDDEN, HD, HH, HDW, SH, 1, 1.f, nullptr, 0);
    gemm64<true,  false><<<dim3(2, 32, NKV), blk>>>(vh, vw, vb, SEQ, HD, HIDDEN,
        HIDDEN, HIDDEN, HD, HH, HDW, SH, 1, 1.f, nullptr, 0);

    // RoPE on q and k
    rope_k<<<(NH  * SEQ * 64 + 255) / 256, blk>>>(qb, pos, NH);
    rope_k<<<(NKV * SEQ * 64 + 255) / 256, blk>>>(kb, pos, NKV);

    // scores[n,l,s] = (q . k)/sqrt(d) + mask   (NT, GQA via bdiv=8, causal block skip)
    gemm64<true,  true ><<<dim3(32, 32, NH), blk>>>(qb, kb, sb, SEQ, SEQ, HD,
        HD, HD, SEQ, SH, SH, SS, 8, isqrt, mask, 0);

    // softmax over rows
    softmax_k<<<NH * SEQ, blk>>>(sb);

    // attn[n,l,h] = P @ V   (NN, K capped by causality)
    gemm64<false, false><<<dim3(2, 32, NH),  blk>>>(sb, vb, ab, SEQ, HD, SEQ,
        SEQ, HD, HD, SS, SH, SH, 8, 1.f, nullptr, 1);

    // out[n,l,d] = attn[n,l,:] . o_w[d, n*128 + :]   (NT, B offset n*128 via sB=128)
    gemm64<true,  false><<<dim3(32, 32, NH), blk>>>(ab, ow, out, SEQ, HIDDEN, HD,
        HD, HIDDEN, HIDDEN, SH, (long)HD, HH, 1, 1.f, nullptr, 0);
}

// round 3
// speedup vs baseline: 1.5698x; 1.5698x over previous
#include <cuda_runtime.h>
#include <cuda_fp16.h>
#include <math.h>
#include <stdint.h>

#define SEQ     2048
#define HIDDEN  2048
#define HD      128
#define NH      16
#define NKV     2

// ---------------- scratch (device globals) ----------------
__device__ __align__(16) float g_q[(size_t)NH  * SEQ * HD];   // 16 MB
__device__ __align__(16) float g_k[(size_t)NKV * SEQ * HD];   // 2 MB
__device__ __align__(16) float g_v[(size_t)NKV * SEQ * HD];   // 2 MB
__device__ __align__(16) float g_vt[(size_t)NKV * HD * SEQ];  // 2 MB (V transposed)
__device__ __align__(16) float g_s[(size_t)NH  * SEQ * SEQ];  // 256 MB
__device__ __align__(16) float g_a[(size_t)NH  * SEQ * HD];   // 16 MB

// ================= helpers =================
__device__ __forceinline__ uint32_t smem_u32(const void* p) {
    uint32_t a;
    asm("{ .reg .u64 t; cvta.to.shared.u64 t, %1; cvt.u32.u64 %0, t; }" : "=r"(a) : "l"(p));
    return a;
}

#define LDSM4(r0, r1, r2, r3, addr) \
    asm volatile("ldmatrix.sync.aligned.m8n8.x4.shared.b16 {%0,%1,%2,%3}, [%4];" \
                 : "=r"(r0), "=r"(r1), "=r"(r2), "=r"(r3) : "r"(addr))

#define MMA16816(c, a, b) \
    asm volatile("mma.sync.aligned.m16n8k16.row.col.f32.f16.f16.f32 " \
                 "{%0,%1,%2,%3}, {%4,%5,%6,%7}, {%8,%9}, {%0,%1,%2,%3};" \
                 : "+f"((c)[0]), "+f"((c)[1]), "+f"((c)[2]), "+f"((c)[3]) \
                 : "r"((a)[0]), "r"((a)[1]), "r"((a)[2]), "r"((a)[3]), \
                   "r"((b)[0]), "r"((b)[1]))

// SMEM tile layout constants (f16, K-chunk = 32, row stride 80 bytes)
#define KC        32
#define ROWB      80
#define TILEB     (128 * ROWB)       // 10240
#define BUFB      (4 * TILEB)        // Ah, Al, Bh, Bl
#define SMB       (2 * BUFB)         // double buffered = 81920

// convert 16 fp32 -> 8 u32 hi-f16x2 + 8 u32 lo-f16x2
__device__ __forceinline__ void cvt_split16(const float4* __restrict__ p,
                                            uint32_t* __restrict__ hw,
                                            uint32_t* __restrict__ lw)
{
    float4 f0 = p[0], f1 = p[1], f2 = p[2], f3 = p[3];
    float xs[16] = {f0.x, f0.y, f0.z, f0.w, f1.x, f1.y, f1.z, f1.w,
                    f2.x, f2.y, f2.z, f2.w, f3.x, f3.y, f3.z, f3.w};
#pragma unroll
    for (int q = 0; q < 8; q++) {
        float a0 = xs[2 * q], a1 = xs[2 * q + 1];
        __half2 h = __float22half2_rn(make_float2(a0, a1));
        float2 hf = __half22float2(h);
        __half2 l = __float22half2_rn(make_float2(a0 - hf.x, a1 - hf.y));
        hw[q] = *reinterpret_cast<uint32_t*>(&h);
        lw[q] = *reinterpret_cast<uint32_t*>(&l);
    }
}

// load 128x32 fp32 tiles of A and B at k0, split to hi/lo f16 SMEM tiles
__device__ __forceinline__ void load_tiles(char* __restrict__ buf,
                                           const float* __restrict__ A,
                                           const float* __restrict__ B,
                                           int lda, int ldb, int k0, int tid)
{
    const int row  = tid >> 1;
    const int half = tid & 1;
    const int off  = row * ROWB + half * 32;
    uint32_t hw[8], lw[8];

    cvt_split16((const float4*)(A + (long)row * lda + k0 + half * 16), hw, lw);
    *(uint4*)(buf + off)                 = make_uint4(hw[0], hw[1], hw[2], hw[3]);
    *(uint4*)(buf + off + 16)            = make_uint4(hw[4], hw[5], hw[6], hw[7]);
    *(uint4*)(buf + TILEB + off)         = make_uint4(lw[0], lw[1], lw[2], lw[3]);
    *(uint4*)(buf + TILEB + off + 16)    = make_uint4(lw[4], lw[5], lw[6], lw[7]);

    cvt_split16((const float4*)(B + (long)row * ldb + k0 + half * 16), hw, lw);
    *(uint4*)(buf + 2 * TILEB + off)      = make_uint4(hw[0], hw[1], hw[2], hw[3]);
    *(uint4*)(buf + 2 * TILEB + off + 16) = make_uint4(hw[4], hw[5], hw[6], hw[7]);
    *(uint4*)(buf + 3 * TILEB + off)      = make_uint4(lw[0], lw[1], lw[2], lw[3]);
    *(uint4*)(buf + 3 * TILEB + off + 16) = make_uint4(lw[4], lw[5], lw[6], lw[7]);
}

// ================= split-f16 HMMA NT GEMM =================
// C[M,N] = A[M,K] @ B[N,K]^T  (fp32 in/out; hi/lo f16 split, 3 MMA terms, fp32 accum)
// CTA tile 128x128, K chunks of 32, double-buffered SMEM, 8 warps (2M x 4N).
// SCORES: c = c*scale + mask; blocks fully above diagonal copy mask only.
// CAUSAL: cap K at m0+128.
template<bool SCORES, bool CAUSAL>
__global__ __launch_bounds__(256, 1)
void tgemm(const float* __restrict__ Ab, const float* __restrict__ Bb,
           float* __restrict__ Cb, int K, int lda, int ldb, int ldc,
           long sA, long sB, long sC, int bdiv, float scale,
           const float* __restrict__ mask)
{
    extern __shared__ char dsm[];
    const int tid  = threadIdx.x;
    const int wid  = tid >> 5;
    const int lane = tid & 31;
    const int wm   = (wid >> 2) << 6;   // warp M offset (0/64)
    const int wn   = (wid & 3) << 5;    // warp N offset (0/32/64/96)
    const int z    = blockIdx.z;
    const int m0   = blockIdx.y << 7;
    const int n0   = blockIdx.x << 7;

    const float* A = Ab + (long)z * sA + (long)m0 * lda;
    const float* B = Bb + (long)(z / bdiv) * sB + (long)n0 * ldb;
    float*       C = Cb + (long)z * sC;

    const bool skip = SCORES && (n0 > m0 + 127);

    if (skip) {  // epilogue-only: copy mask
        for (int j = tid; j < 128 * 32; j += 256) {
            const int r = j >> 5, c4 = (j & 31) << 2;
            *(float4*)(C + (long)(m0 + r) * ldc + n0 + c4) =
                *(const float4*)(mask + (long)(m0 + r) * SEQ + n0 + c4);
        }
        return;
    }

    int nch = K >> 5;
    if (CAUSAL) { int ke = m0 + 128; if (ke < K) nch = ke >> 5; }

    float acc[4][4][4];
#pragma unroll
    for (int i = 0; i < 4; i++)
#pragma unroll
        for (int j = 0; j < 4; j++)
#pragma unroll
            for (int q = 0; q < 4; q++) acc[i][j][q] = 0.f;

    // precomputed ldmatrix lane offsets
    const uint32_t smbase = smem_u32(dsm);
    const int a_row  = wm + (lane & 15);
    const int a_koff = (lane >> 4) << 4;                        // bytes
    const int b_row  = wn + (lane & 7) + ((lane >> 4) & 1) * 8;
    const int b_koff = ((lane >> 3) & 1) << 4;                  // bytes

    load_tiles(dsm, A, B, lda, ldb, 0, tid);
    __syncthreads();

    for (int i = 0; i < nch; i++) {
        if (i + 1 < nch)
            load_tiles(dsm + ((i + 1) & 1) * BUFB, A, B, lda, ldb, (i + 1) << 5, tid);

        const uint32_t tb = smbase + (i & 1) * BUFB;
#pragma unroll
        for (int ks = 0; ks < 2; ks++) {
            uint32_t ah[4][4], al[4][4], bh[4][2], bl[4][2];
            const uint32_t ka = ks * 32 + a_koff;
            const uint32_t kb = ks * 32 + b_koff;
#pragma unroll
            for (int mi = 0; mi < 4; mi++) {
                LDSM4(ah[mi][0], ah[mi][1], ah[mi][2], ah[mi][3],
                      tb + (uint32_t)(a_row + mi * 16) * ROWB + ka);
                LDSM4(al[mi][0], al[mi][1], al[mi][2], al[mi][3],
                      tb + TILEB + (uint32_t)(a_row + mi * 16) * ROWB + ka);
            }
#pragma unroll
            for (int p = 0; p < 2; p++) {
                uint32_t r0, r1, r2, r3;
                LDSM4(r0, r1, r2, r3,
                      tb + 2 * TILEB + (uint32_t)(b_row + p * 16) * ROWB + kb);
                bh[2 * p][0] = r0; bh[2 * p][1] = r1;
                bh[2 * p + 1][0] = r2; bh[2 * p + 1][1] = r3;
                LDSM4(r0, r1, r2, r3,
                      tb + 3 * TILEB + (uint32_t)(b_row + p * 16) * ROWB + kb);
                bl[2 * p][0] = r0; bl[2 * p][1] = r1;
                bl[2 * p + 1][0] = r2; bl[2 * p + 1][1] = r3;
            }
#pragma unroll
            for (int mi = 0; mi < 4; mi++)
#pragma unroll
                for (int ni = 0; ni < 4; ni++) {
                    MMA16816(acc[mi][ni], ah[mi], bh[ni]);
                    MMA16816(acc[mi][ni], al[mi], bh[ni]);
                    MMA16816(acc[mi][ni], ah[mi], bl[ni]);
                }
        }
        __syncthreads();
    }

    // ---------------- epilogue ----------------
    const int g = lane >> 2, t = lane & 3;
#pragma unroll
    for (int mi = 0; mi < 4; mi++) {
        const int r0 = m0 + wm + mi * 16 + g;
#pragma unroll
        for (int ni = 0; ni < 4; ni++) {
            const int cc = n0 + wn + ni * 8 + t * 2;
            float2 v01 = make_float2(acc[mi][ni][0], acc[mi][ni][1]);
            float2 v23 = make_float2(acc[mi][ni][2], acc[mi][ni][3]);
            if (SCORES) {
                const float2 m01 = *(const float2*)(mask + (long)r0 * SEQ + cc);
                const float2 m23 = *(const float2*)(mask + (long)(r0 + 8) * SEQ + cc);
                v01.x = v01.x * scale + m01.x;  v01.y = v01.y * scale + m01.y;
                v23.x = v23.x * scale + m23.x;  v23.y = v23.y * scale + m23.y;
            }
            *(float2*)(C + (long)r0 * ldc + cc)       = v01;
            *(float2*)(C + (long)(r0 + 8) * ldc + cc) = v23;
        }
    }
}

// ---------------- RoPE (in-place, fp32 Cody-Waite) ----------------
__global__ __launch_bounds__(256)
void rope_k(float* __restrict__ buf, const int* __restrict__ pos, int heads)
{
    int idx = blockIdx.x * 256 + threadIdx.x;
    int total = heads * SEQ * 64;
    if (idx >= total) return;
    int i = idx & 63;
    int l = (idx >> 6) % SEQ;
    int n = idx / (SEQ * 64);

    float invf = exp2f(-(float)i * 0.31143075889569023f);
    float ang  = (float)pos[l] * invf;
    float q  = rintf(ang * 0.15915494309189535f);
    float r  = ang - q * 6.28125f;
    r        = r   - q * 1.9353071795864769e-3f;
    float s, c;
    sincosf(r, &s, &c);

    float* p = buf + ((long)n * SEQ + l) * HD;
    float x1 = p[i], x2 = p[i + 64];
    p[i]      = x1 * c - x2 * s;
    p[i + 64] = x2 * c + x1 * s;
}

// ---------------- V transpose: [kv][S][128] -> [kv][128][S] ----------------
__global__ __launch_bounds__(256)
void transpose_v(const float* __restrict__ v, float* __restrict__ vt)
{
    __shared__ float t[32][33];
    int h  = blockIdx.z;
    int s0 = blockIdx.x * 32, d0 = blockIdx.y * 32;
    const float* src = v + ((long)h * SEQ + s0) * HD + d0;
#pragma unroll
    for (int yy = threadIdx.y; yy < 32; yy += 8)
        t[yy][threadIdx.x] = src[yy * HD + threadIdx.x];
    __syncthreads();
    float* dst = vt + ((long)h * HD + d0) * SEQ + s0;
#pragma unroll
    for (int yy = threadIdx.y; yy < 32; yy += 8)
        dst[(long)yy * SEQ + threadIdx.x] = t[threadIdx.x][yy];
}

// ---------------- row softmax (SMEM-staged) ----------------
__global__ __launch_bounds__(256)
void softmax_k(float* __restrict__ sc)
{
    __shared__ float row[SEQ];
    __shared__ float red[256];
    float* p = sc + (long)blockIdx.x * SEQ;
    const int t = threadIdx.x;

    float m = -1e30f;
    for (int j = t; j < SEQ / 4; j += 256) {
        float4 v = ((const float4*)p)[j];
        ((float4*)row)[j] = v;
        m = fmaxf(fmaxf(m, fmaxf(v.x, v.y)), fmaxf(v.z, v.w));
    }
    red[t] = m; __syncthreads();
    for (int st = 128; st > 0; st >>= 1) {
        if (t < st) red[t] = fmaxf(red[t], red[t + st]);
        __syncthreads();
    }
    m = red[0];
    __syncthreads();

    float sum = 0.f;
    for (int j = t; j < SEQ; j += 256) {
        float e = expf(row[j] - m);
        row[j] = e;
        sum += e;
    }
    red[t] = sum; __syncthreads();
    for (int st = 128; st > 0; st >>= 1) {
        if (t < st) red[t] += red[t + st];
        __syncthreads();
    }
    float inv = 1.f / red[0];
    __syncthreads();
    for (int j = t; j < SEQ / 4; j += 256) {
        float4 v = ((float4*)row)[j];
        v.x *= inv; v.y *= inv; v.z *= inv; v.w *= inv;
        ((float4*)p)[j] = v;
    }
}

// ---------------- launch ----------------
extern "C" void kernel_launch(void* const* d_in, const int* in_sizes, int n_in,
                              void* d_out, int out_size)
{
    const float* qh   = (const float*)d_in[0];
    const float* kh   = (const float*)d_in[1];
    const float* vh   = (const float*)d_in[2];
    const float* mask = (const float*)d_in[3];
    const int*   pos  = (const int*)  d_in[4];
    const float* qw   = (const float*)d_in[5];
    const float* kw   = (const float*)d_in[6];
    const float* vw   = (const float*)d_in[7];
    const float* ow   = (const float*)d_in[8];
    float*       out  = (float*)d_out;

    float *qb, *kb, *vb, *vt, *sb, *ab;
    cudaGetSymbolAddress((void**)&qb, g_q);
    cudaGetSymbolAddress((void**)&kb, g_k);
    cudaGetSymbolAddress((void**)&vb, g_v);
    cudaGetSymbolAddress((void**)&vt, g_vt);
    cudaGetSymbolAddress((void**)&sb, g_s);
    cudaGetSymbolAddress((void**)&ab, g_a);

    cudaFuncSetAttribute(tgemm<false, false>, cudaFuncAttributeMaxDynamicSharedMemorySize, SMB);
    cudaFuncSetAttribute(tgemm<true,  false>, cudaFuncAttributeMaxDynamicSharedMemorySize, SMB);
    cudaFuncSetAttribute(tgemm<false, true >, cudaFuncAttributeMaxDynamicSharedMemorySize, SMB);

    const long HH  = (long)SEQ * HIDDEN;
    const long HDW = (long)HD * HIDDEN;
    const long SH  = (long)SEQ * HD;
    const long SS  = (long)SEQ * SEQ;
    const float isqrt = 0.08838834764831845f;

    // Q/K/V projections (NT): C[l,h] = X[l,:] . W[h,:]
    tgemm<false, false><<<dim3(1, 16, NH),  256, SMB>>>(qh, qw, qb, HIDDEN,
        HIDDEN, HIDDEN, HD, HH, HDW, SH, 1, 1.f, nullptr);
    tgemm<false, false><<<dim3(1, 16, NKV), 256, SMB>>>(kh, kw, kb, HIDDEN,
        HIDDEN, HIDDEN, HD, HH, HDW, SH, 1, 1.f, nullptr);
    tgemm<false, false><<<dim3(1, 16, NKV), 256, SMB>>>(vh, vw, vb, HIDDEN,
        HIDDEN, HIDDEN, HD, HH, HDW, SH, 1, 1.f, nullptr);

    // RoPE on q and k
    rope_k<<<(NH  * SEQ * 64 + 255) / 256, 256>>>(qb, pos, NH);
    rope_k<<<(NKV * SEQ * 64 + 255) / 256, 256>>>(kb, pos, NKV);

    // V transpose for NT PV
    transpose_v<<<dim3(64, 4, NKV), dim3(32, 8)>>>(vb, vt);

    // scores = (q . k)/sqrt(d) + mask  (GQA bdiv=8, upper blocks -> mask copy)
    tgemm<true, false><<<dim3(16, 16, NH), 256, SMB>>>(qb, kb, sb, HD,
        HD, HD, SEQ, SH, SH, SS, 8, isqrt, mask);

    // softmax rows
    softmax_k<<<NH * SEQ, 256>>>(sb);

    // attn = P @ V^T (NT, causal K cap)
    tgemm<false, true><<<dim3(1, 16, NH), 256, SMB>>>(sb, vt, ab, SEQ,
        SEQ, SEQ, HD, SS, SH, SH, 8, 1.f, nullptr);

    // out[l,d] = attn[l,:] . ow[d, z*128 + :]  (B offset via sB=128)
    tgemm<false, false><<<dim3(16, 16, NH), 256, SMB>>>(ab, ow, out, HD,
        HD, HIDDEN, HIDDEN, SH, (long)HD, HH, 1, 1.f, nullptr);
}

// round 4
// speedup vs baseline: 2.9620x; 1.8869x over previous
#include <cuda_runtime.h>
#include <cuda_fp16.h>
#include <math.h>
#include <stdint.h>

#define SEQ     2048
#define HIDDEN  2048
#define HD      128
#define NH      16
#define NKV     2

// ---------------- scratch (device globals) ----------------
__device__ __align__(16) float  g_q [(size_t)NH  * SEQ * HD];
__device__ __align__(16) float  g_k [(size_t)NKV * SEQ * HD];
__device__ __align__(16) float  g_v [(size_t)NKV * SEQ * HD];
__device__ __align__(16) float  g_vt[(size_t)NKV * HD * SEQ];
__device__ __align__(16) float  g_a [(size_t)NH  * SEQ * HD];
__device__ __align__(16) __half g_qh [(size_t)NH  * SEQ * HD];
__device__ __align__(16) __half g_ql [(size_t)NH  * SEQ * HD];
__device__ __align__(16) __half g_kh [(size_t)NKV * SEQ * HD];
__device__ __align__(16) __half g_kl [(size_t)NKV * SEQ * HD];
__device__ __align__(16) __half g_vth[(size_t)NKV * HD * SEQ];
__device__ __align__(16) __half g_vtl[(size_t)NKV * HD * SEQ];

// ================= helpers =================
__device__ __forceinline__ uint32_t smem_u32(const void* p) {
    uint32_t a;
    asm("{ .reg .u64 t; cvta.to.shared.u64 t, %1; cvt.u32.u64 %0, t; }" : "=r"(a) : "l"(p));
    return a;
}

#define LDSM4(r0, r1, r2, r3, addr) \
    asm volatile("ldmatrix.sync.aligned.m8n8.x4.shared.b16 {%0,%1,%2,%3}, [%4];" \
                 : "=r"(r0), "=r"(r1), "=r"(r2), "=r"(r3) : "r"(addr))

#define MMA16816(c, a, b) \
    asm volatile("mma.sync.aligned.m16n8k16.row.col.f32.f16.f16.f32 " \
                 "{%0,%1,%2,%3}, {%4,%5,%6,%7}, {%8,%9}, {%0,%1,%2,%3};" \
                 : "+f"((c)[0]), "+f"((c)[1]), "+f"((c)[2]), "+f"((c)[3]) \
                 : "r"((a)[0]), "r"((a)[1]), "r"((a)[2]), "r"((a)[3]), \
                   "r"((b)[0]), "r"((b)[1]))

#define CPA16(dst, src) \
    asm volatile("cp.async.cg.shared.global [%0], [%1], 16;" :: "r"(dst), "l"(src))
#define CPA_COMMIT()  asm volatile("cp.async.commit_group;")
#define CPA_WAIT0()   asm volatile("cp.async.wait_group 0;")
#define CPA_WAIT1()   asm volatile("cp.async.wait_group 1;")

// ================= projection GEMM (split-f16 HMMA, NT) =================
#define ROWB  80
#define TILEB (128 * ROWB)
#define BUFB  (4 * TILEB)
#define GSMB  (2 * BUFB)

__device__ __forceinline__ void cvt_split16(const float* __restrict__ xs,
                                            uint32_t* __restrict__ hw,
                                            uint32_t* __restrict__ lw)
{
#pragma unroll
    for (int q = 0; q < 8; q++) {
        float a0 = xs[2 * q], a1 = xs[2 * q + 1];
        __half2 h = __floats2half2_rn(a0, a1);
        float2 hf = __half22float2(h);
        __half2 l = __floats2half2_rn(a0 - hf.x, a1 - hf.y);
        hw[q] = *reinterpret_cast<uint32_t*>(&h);
        lw[q] = *reinterpret_cast<uint32_t*>(&l);
    }
}

__global__ __launch_bounds__(256, 1)
void tgemm(const float* __restrict__ Ab, const float* __restrict__ Bb,
           float* __restrict__ Cb, int K, int lda, int ldb, int ldc,
           long sA, long sB, long sC)
{
    extern __shared__ char dsm[];
    const int tid  = threadIdx.x;
    const int wid  = tid >> 5;
    const int lane = tid & 31;
    const int wm   = (wid >> 2) << 6;
    const int wn   = (wid & 3) << 5;
    const int z    = blockIdx.z;
    const int m0   = blockIdx.y << 7;
    const int n0   = blockIdx.x << 7;

    const float* A = Ab + (long)z * sA + (long)m0 * lda;
    const float* B = Bb + (long)z * sB + (long)n0 * ldb;
    float*       C = Cb + (long)z * sC;

    const int nch = K >> 5;
    const int lrow = tid >> 1, lhalf = tid & 1;
    const int soff = lrow * ROWB + lhalf * 32;

    float acc[4][4][4];
#pragma unroll
    for (int i = 0; i < 4; i++)
#pragma unroll
        for (int j = 0; j < 4; j++)
#pragma unroll
            for (int q = 0; q < 4; q++) acc[i][j][q] = 0.f;

    const uint32_t smbase = smem_u32(dsm);
    const int a_row  = wm + (lane & 15);
    const int a_koff = (lane >> 4) << 4;
    const int b_row  = wn + (lane & 7) + ((lane >> 4) & 1) * 8;
    const int b_koff = ((lane >> 3) & 1) << 4;

    float ra[16], rb[16];
    // prologue: load chunk 0, store chunk 0
    {
        const float4* pa = (const float4*)(A + (long)lrow * lda + lhalf * 16);
        const float4* pb = (const float4*)(B + (long)lrow * ldb + lhalf * 16);
#pragma unroll
        for (int q = 0; q < 4; q++) { *(float4*)(ra + 4 * q) = pa[q]; *(float4*)(rb + 4 * q) = pb[q]; }
        uint32_t hw[8], lw[8];
        cvt_split16(ra, hw, lw);
        *(uint4*)(dsm + soff)              = make_uint4(hw[0], hw[1], hw[2], hw[3]);
        *(uint4*)(dsm + soff + 16)         = make_uint4(hw[4], hw[5], hw[6], hw[7]);
        *(uint4*)(dsm + TILEB + soff)      = make_uint4(lw[0], lw[1], lw[2], lw[3]);
        *(uint4*)(dsm + TILEB + soff + 16) = make_uint4(lw[4], lw[5], lw[6], lw[7]);
        cvt_split16(rb, hw, lw);
        *(uint4*)(dsm + 2 * TILEB + soff)      = make_uint4(hw[0], hw[1], hw[2], hw[3]);
        *(uint4*)(dsm + 2 * TILEB + soff + 16) = make_uint4(hw[4], hw[5], hw[6], hw[7]);
        *(uint4*)(dsm + 3 * TILEB + soff)      = make_uint4(lw[0], lw[1], lw[2], lw[3]);
        *(uint4*)(dsm + 3 * TILEB + soff + 16) = make_uint4(lw[4], lw[5], lw[6], lw[7]);
    }
    __syncthreads();

    for (int i = 0; i < nch; i++) {
        // 1) issue next chunk's LDGs early (latency covered by MMA below)
        if (i + 1 < nch) {
            const int k0 = (i + 1) << 5;
            const float4* pa = (const float4*)(A + (long)lrow * lda + k0 + lhalf * 16);
            const float4* pb = (const float4*)(B + (long)lrow * ldb + k0 + lhalf * 16);
#pragma unroll
            for (int q = 0; q < 4; q++) { *(float4*)(ra + 4 * q) = pa[q]; *(float4*)(rb + 4 * q) = pb[q]; }
        }
        // 2) MMA on current buffer
        const uint32_t tb = smbase + (i & 1) * BUFB;
#pragma unroll
        for (int ks = 0; ks < 2; ks++) {
            uint32_t ah[4][4], al[4][4], bh[4][2], bl[4][2];
            const uint32_t ka = ks * 32 + a_koff;
            const uint32_t kb = ks * 32 + b_koff;
#pragma unroll
            for (int mi = 0; mi < 4; mi++) {
                LDSM4(ah[mi][0], ah[mi][1], ah[mi][2], ah[mi][3],
                      tb + (uint32_t)(a_row + mi * 16) * ROWB + ka);
                LDSM4(al[mi][0], al[mi][1], al[mi][2], al[mi][3],
                      tb + TILEB + (uint32_t)(a_row + mi * 16) * ROWB + ka);
            }
#pragma unroll
            for (int p = 0; p < 2; p++) {
                uint32_t r0, r1, r2, r3;
                LDSM4(r0, r1, r2, r3, tb + 2 * TILEB + (uint32_t)(b_row + p * 16) * ROWB + kb);
                bh[2 * p][0] = r0; bh[2 * p][1] = r1; bh[2 * p + 1][0] = r2; bh[2 * p + 1][1] = r3;
                LDSM4(r0, r1, r2, r3, tb + 3 * TILEB + (uint32_t)(b_row + p * 16) * ROWB + kb);
                bl[2 * p][0] = r0; bl[2 * p][1] = r1; bl[2 * p + 1][0] = r2; bl[2 * p + 1][1] = r3;
            }
#pragma unroll
            for (int mi = 0; mi < 4; mi++)
#pragma unroll
                for (int ni = 0; ni < 4; ni++) {
                    MMA16816(acc[mi][ni], ah[mi], bh[ni]);
                    MMA16816(acc[mi][ni], al[mi], bh[ni]);
                    MMA16816(acc[mi][ni], ah[mi], bl[ni]);
                }
        }
        // 3) cvt + store next chunk into the other buffer
        if (i + 1 < nch) {
            char* buf = dsm + ((i + 1) & 1) * BUFB;
            uint32_t hw[8], lw[8];
            cvt_split16(ra, hw, lw);
            *(uint4*)(buf + soff)              = make_uint4(hw[0], hw[1], hw[2], hw[3]);
            *(uint4*)(buf + soff + 16)         = make_uint4(hw[4], hw[5], hw[6], hw[7]);
            *(uint4*)(buf + TILEB + soff)      = make_uint4(lw[0], lw[1], lw[2], lw[3]);
            *(uint4*)(buf + TILEB + soff + 16) = make_uint4(lw[4], lw[5], lw[6], lw[7]);
            cvt_split16(rb, hw, lw);
            *(uint4*)(buf + 2 * TILEB + soff)      = make_uint4(hw[0], hw[1], hw[2], hw[3]);
            *(uint4*)(buf + 2 * TILEB + soff + 16) = make_uint4(hw[4], hw[5], hw[6], hw[7]);
            *(uint4*)(buf + 3 * TILEB + soff)      = make_uint4(lw[0], lw[1], lw[2], lw[3]);
            *(uint4*)(buf + 3 * TILEB + soff + 16) = make_uint4(lw[4], lw[5], lw[6], lw[7]);
        }
        __syncthreads();
    }

    // epilogue
    const int g = lane >> 2, t = lane & 3;
#pragma unroll
    for (int mi = 0; mi < 4; mi++) {
        const int r0 = m0 + wm + mi * 16 + g;
#pragma unroll
        for (int ni = 0; ni < 4; ni++) {
            const int cc = n0 + wn + ni * 8 + t * 2;
            *(float2*)(C + (long)r0 * ldc + cc)       = make_float2(acc[mi][ni][0], acc[mi][ni][1]);
            *(float2*)(C + (long)(r0 + 8) * ldc + cc) = make_float2(acc[mi][ni][2], acc[mi][ni][3]);
        }
    }
}

// ================= flash attention (split-f16 HMMA, online softmax) =================
// smem layout (f16, padded rows): Qh/Ql 128x128 (stride 272B), K buf 64x128 (272B), V^T buf 128x64 (144B)
#define QL_OFF 34816
#define K_OFF  69632
#define V_OFF  139264
#define FSMEM  212992
#define FC     0.12751744f   // log2(e) / sqrt(128)

__device__ __forceinline__ void kv_prefetch(uint32_t smb, int buf, int kv0,
    const __half* __restrict__ khp, const __half* __restrict__ klp,
    const __half* __restrict__ vhp, const __half* __restrict__ vlp, int tid)
{
#pragma unroll
    for (int i = 0; i < 8; i++) {
        int t = tid + (i << 8);
        int unit = t & 15, row = (t >> 4) & 63, hl = t >> 10;
        const __half* src = (hl ? klp : khp) + (long)(kv0 + row) * HD + unit * 8;
        uint32_t dst = smb + K_OFF + buf * 34816 + hl * 17408 + row * 272 + unit * 16;
        CPA16(dst, src);
    }
#pragma unroll
    for (int i = 0; i < 8; i++) {
        int t = tid + (i << 8);
        int unit = t & 7, row = (t >> 3) & 127, hl = t >> 10;
        const __half* src = (hl ? vlp : vhp) + (long)row * SEQ + kv0 + unit * 8;
        uint32_t dst = smb + V_OFF + buf * 36864 + hl * 18432 + row * 144 + unit * 16;
        CPA16(dst, src);
    }
}

__global__ __launch_bounds__(256, 1)
void flash_k(const __half* __restrict__ qhg, const __half* __restrict__ qlg,
             const __half* __restrict__ khg, const __half* __restrict__ klg,
             const __half* __restrict__ vhg, const __half* __restrict__ vlg,
             float* __restrict__ oa)
{
    extern __shared__ char dsm[];
    const uint32_t smb = smem_u32(dsm);
    const int tid  = threadIdx.x;
    const int w    = tid >> 5;
    const int lane = tid & 31;
    const int z    = blockIdx.x;          // head
    const int mb   = 15 - blockIdx.y;     // heavy blocks first
    const int kvh  = z >> 3;
    const int m0   = mb << 7;
    const int nt   = (mb + 1) << 1;

    const __half* qhp = qhg + ((long)z * SEQ + m0) * HD;
    const __half* qlp = qlg + ((long)z * SEQ + m0) * HD;
    const __half* khp = khg + (long)kvh * SEQ * HD;
    const __half* klp = klg + (long)kvh * SEQ * HD;
    const __half* vhp = vhg + (long)kvh * HD * SEQ;
    const __half* vlp = vlg + (long)kvh * HD * SEQ;

    // Q tiles -> smem (one-time)
#pragma unroll
    for (int i = 0; i < 16; i++) {
        int t = tid + (i << 8);
        int unit = t & 15, row = (t >> 4) & 127, hl = t >> 11;
        const __half* src = (hl ? qlp : qhp) + (long)row * HD + unit * 8;
        uint32_t dst = smb + hl * QL_OFF + row * 272 + unit * 16;
        CPA16(dst, src);
    }
    CPA_COMMIT();
    kv_prefetch(smb, 0, 0, khp, klp, vhp, vlp, tid);
    CPA_COMMIT();

    float o[16][4];
#pragma unroll
    for (int nb = 0; nb < 16; nb++)
#pragma unroll
        for (int q = 0; q < 4; q++) o[nb][q] = 0.f;
    float mr0 = -1e30f, mr1 = -1e30f, l0 = 0.f, l1 = 0.f;

    const int wrow = m0 + (w << 4);
    const uint32_t qa_h = smb + (uint32_t)(wrow - m0 + (lane & 15)) * 272 + ((lane >> 4) << 4);
    const uint32_t qa_l = qa_h + QL_OFF;
    const uint32_t brow = (lane & 7) + ((lane >> 4) & 1) * 8;
    const uint32_t bko  = ((lane >> 3) & 1) << 4;

    int buf = 0;
    for (int it = 0; it < nt; it++) {
        if (it + 1 < nt) {
            kv_prefetch(smb, buf ^ 1, (it + 1) << 6, khp, klp, vhp, vlp, tid);
            CPA_COMMIT();
            CPA_WAIT1();
        } else {
            CPA_WAIT0();
        }
        __syncthreads();

        const int kv0 = it << 6;
        if (kv0 <= wrow + 15) {
            const uint32_t kb_h = smb + K_OFF + buf * 34816;
            const uint32_t kb_l = kb_h + 17408;
            const uint32_t vb_h = smb + V_OFF + buf * 36864;
            const uint32_t vb_l = vb_h + 18432;

            float s[8][4];
#pragma unroll
            for (int nb = 0; nb < 8; nb++)
#pragma unroll
                for (int q = 0; q < 4; q++) s[nb][q] = 0.f;

            // ---- scores: s = Q . K^T (3-term split) ----
#pragma unroll
            for (int j = 0; j < 8; j++) {
                uint32_t ah[4], al[4];
                LDSM4(ah[0], ah[1], ah[2], ah[3], qa_h + j * 32);
                LDSM4(al[0], al[1], al[2], al[3], qa_l + j * 32);
#pragma unroll
                for (int g16 = 0; g16 < 4; g16++) {
                    uint32_t bh[4], bl[4];
                    const uint32_t ba = (uint32_t)(g16 * 16 + brow) * 272 + bko + j * 32;
                    LDSM4(bh[0], bh[1], bh[2], bh[3], kb_h + ba);
                    LDSM4(bl[0], bl[1], bl[2], bl[3], kb_l + ba);
                    MMA16816(s[2 * g16],     ah, bh);
                    MMA16816(s[2 * g16],     al, bh);
                    MMA16816(s[2 * g16],     ah, bl);
                    MMA16816(s[2 * g16 + 1], ah, bh + 2);
                    MMA16816(s[2 * g16 + 1], al, bh + 2);
                    MMA16816(s[2 * g16 + 1], ah, bl + 2);
                }
            }

            // ---- causal mask ----
            const int r0 = wrow + (lane >> 2);
            const int c0 = kv0 + ((lane & 3) << 1);
            if (kv0 + 63 > wrow) {
#pragma unroll
                for (int nb = 0; nb < 8; nb++) {
                    const int c = c0 + nb * 8;
                    if (c     > r0    ) s[nb][0] = -1e30f;
                    if (c + 1 > r0    ) s[nb][1] = -1e30f;
                    if (c     > r0 + 8) s[nb][2] = -1e30f;
                    if (c + 1 > r0 + 8) s[nb][3] = -1e30f;
                }
            }

            // ---- online softmax ----
            float tm0 = -1e30f, tm1 = -1e30f;
#pragma unroll
            for (int nb = 0; nb < 8; nb++) {
                tm0 = fmaxf(tm0, fmaxf(s[nb][0], s[nb][1]));
                tm1 = fmaxf(tm1, fmaxf(s[nb][2], s[nb][3]));
            }
            tm0 = fmaxf(tm0, __shfl_xor_sync(0xffffffffu, tm0, 1));
            tm0 = fmaxf(tm0, __shfl_xor_sync(0xffffffffu, tm0, 2));
            tm1 = fmaxf(tm1, __shfl_xor_sync(0xffffffffu, tm1, 1));
            tm1 = fmaxf(tm1, __shfl_xor_sync(0xffffffffu, tm1, 2));
            const float mn0 = fmaxf(mr0, tm0), mn1 = fmaxf(mr1, tm1);
            const float sf0 = exp2f((mr0 - mn0) * FC);
            const float sf1 = exp2f((mr1 - mn1) * FC);
            mr0 = mn0; mr1 = mn1;
            l0 *= sf0;  l1 *= sf1;
#pragma unroll
            for (int nb = 0; nb < 16; nb++) {
                o[nb][0] *= sf0; o[nb][1] *= sf0;
                o[nb][2] *= sf1; o[nb][3] *= sf1;
            }
            float rs0 = 0.f, rs1 = 0.f;
#pragma unroll
            for (int nb = 0; nb < 8; nb++) {
                s[nb][0] = exp2f((s[nb][0] - mn0) * FC); rs0 += s[nb][0];
                s[nb][1] = exp2f((s[nb][1] - mn0) * FC); rs0 += s[nb][1];
                s[nb][2] = exp2f((s[nb][2] - mn1) * FC); rs1 += s[nb][2];
                s[nb][3] = exp2f((s[nb][3] - mn1) * FC); rs1 += s[nb][3];
            }
            rs0 += __shfl_xor_sync(0xffffffffu, rs0, 1);
            rs0 += __shfl_xor_sync(0xffffffffu, rs0, 2);
            rs1 += __shfl_xor_sync(0xffffffffu, rs1, 1);
            rs1 += __shfl_xor_sync(0xffffffffu, rs1, 2);
            l0 += rs0; l1 += rs1;

            // ---- PV: o += P . V (3-term split) ----
#pragma unroll
            for (int j = 0; j < 4; j++) {
                uint32_t pha[4], pla[4];
#pragma unroll
                for (int hquad = 0; hquad < 4; hquad++) {
                    const int nb = 2 * j + (hquad >> 1);
                    const int e  = (hquad & 1) << 1;
                    const float p0 = s[nb][e], p1 = s[nb][e + 1];
                    __half2 h = __floats2half2_rn(p0, p1);
                    float2 hf = __half22float2(h);
                    __half2 l = __floats2half2_rn(p0 - hf.x, p1 - hf.y);
                    // hquad order: 0:(g,k0-7) 1:(g+8,k0-7) 2:(g,k8-15) 3:(g+8,k8-15)
                    const int fi = ((hquad & 1) << 0) | ((hquad >> 1) << 1);
                    pha[(fi & 1) | ((fi >> 1) << 1)] = 0; // placeholder (overwritten below)
                    pha[hquad] = *reinterpret_cast<uint32_t*>(&h);
                    pla[hquad] = *reinterpret_cast<uint32_t*>(&l);
                }
                // reorder: frag a0=(g,klo)=s[2j][0:1], a1=(g+8,klo)=s[2j][2:3],
                //          a2=(g,khi)=s[2j+1][0:1],  a3=(g+8,khi)=s[2j+1][2:3]
                // hquad mapping produced: 0 -> s[2j][0:1], 1 -> s[2j][2:3],
                //                         2 -> s[2j+1][0:1], 3 -> s[2j+1][2:3]  (already correct)
#pragma unroll
                for (int g16 = 0; g16 < 8; g16++) {
                    uint32_t bh[4], bl[4];
                    const uint32_t ba = (uint32_t)(g16 * 16 + brow) * 144 + bko + j * 32;
                    LDSM4(bh[0], bh[1], bh[2], bh[3], vb_h + ba);
                    LDSM4(bl[0], bl[1], bl[2], bl[3], vb_l + ba);
                    MMA16816(o[2 * g16],     pha, bh);
                    MMA16816(o[2 * g16],     pla, bh);
                    MMA16816(o[2 * g16],     pha, bl);
                    MMA16816(o[2 * g16 + 1], pha, bh + 2);
                    MMA16816(o[2 * g16 + 1], pla, bh + 2);
                    MMA16816(o[2 * g16 + 1], pha, bl + 2);
                }
            }
        }
        __syncthreads();
        buf ^= 1;
    }

    // ---- epilogue: normalize and write ----
    const float inv0 = 1.f / l0, inv1 = 1.f / l1;
    const int r0 = wrow + (lane >> 2);
    float* p0 = oa + ((long)z * SEQ + r0) * HD + ((lane & 3) << 1);
    float* p1 = p0 + 8 * HD;
#pragma unroll
    for (int nb = 0; nb < 16; nb++) {
        *(float2*)(p0 + nb * 8) = make_float2(o[nb][0] * inv0, o[nb][1] * inv0);
        *(float2*)(p1 + nb * 8) = make_float2(o[nb][2] * inv1, o[nb][3] * inv1);
    }
}

// ---------------- RoPE (in-place, fp32 Cody-Waite) ----------------
__global__ __launch_bounds__(256)
void rope_k(float* __restrict__ buf, const int* __restrict__ pos, int heads)
{
    int idx = blockIdx.x * 256 + threadIdx.x;
    int total = heads * SEQ * 64;
    if (idx >= total) return;
    int i = idx & 63;
    int l = (idx >> 6) % SEQ;
    int n = idx / (SEQ * 64);

    float invf = exp2f(-(float)i * 0.31143075889569023f);
    float ang  = (float)pos[l] * invf;
    float q  = rintf(ang * 0.15915494309189535f);
    float r  = ang - q * 6.28125f;
    r        = r   - q * 1.9353071795864769e-3f;
    float s, c;
    sincosf(r, &s, &c);

    float* p = buf + ((long)n * SEQ + l) * HD;
    float x1 = p[i], x2 = p[i + 64];
    p[i]      = x1 * c - x2 * s;
    p[i + 64] = x2 * c + x1 * s;
}

// ---------------- V transpose: [kv][S][128] -> [kv][128][S] ----------------
__global__ __launch_bounds__(256)
void transpose_v(const float* __restrict__ v, float* __restrict__ vt)
{
    __shared__ float t[32][33];
    int h  = blockIdx.z;
    int s0 = blockIdx.x * 32, d0 = blockIdx.y * 32;
    const float* src = v + ((long)h * SEQ + s0) * HD + d0;
#pragma unroll
    for (int yy = threadIdx.y; yy < 32; yy += 8)
        t[yy][threadIdx.x] = src[yy * HD + threadIdx.x];
    __syncthreads();
    float* dst = vt + ((long)h * HD + d0) * SEQ + s0;
#pragma unroll
    for (int yy = threadIdx.y; yy < 32; yy += 8)
        dst[(long)yy * SEQ + threadIdx.x] = t[threadIdx.x][yy];
}

// ---------------- fp32 -> (hi, lo) f16 split ----------------
__global__ __launch_bounds__(256)
void split_k(const float* __restrict__ s, __half* __restrict__ h,
             __half* __restrict__ l, int n)
{
    int i = (blockIdx.x * 256 + threadIdx.x) << 2;
    if (i >= n) return;
    float4 v = *(const float4*)(s + i);
    __half2 h01 = __floats2half2_rn(v.x, v.y);
    __half2 h23 = __floats2half2_rn(v.z, v.w);
    float2 f01 = __half22float2(h01), f23 = __half22float2(h23);
    __half2 l01 = __floats2half2_rn(v.x - f01.x, v.y - f01.y);
    __half2 l23 = __floats2half2_rn(v.z - f23.x, v.w - f23.y);
    ((__half2*)(h + i))[0] = h01; ((__half2*)(h + i))[1] = h23;
    ((__half2*)(l + i))[0] = l01; ((__half2*)(l + i))[1] = l23;
}

// ---------------- launch ----------------
extern "C" void kernel_launch(void* const* d_in, const int* in_sizes, int n_in,
                              void* d_out, int out_size)
{
    const float* qhid = (const float*)d_in[0];
    const float* khid = (const float*)d_in[1];
    const float* vhid = (const float*)d_in[2];
    // d_in[3] = attention_mask (causality applied inline)
    const int*   pos  = (const int*)  d_in[4];
    const float* qw   = (const float*)d_in[5];
    const float* kw   = (const float*)d_in[6];
    const float* vw   = (const float*)d_in[7];
    const float* ow   = (const float*)d_in[8];
    float*       out  = (float*)d_out;

    float *qb, *kb, *vb, *vt, *ab;
    __half *qhh, *qll, *khh, *kll, *vth, *vtl;
    cudaGetSymbolAddress((void**)&qb,  g_q);
    cudaGetSymbolAddress((void**)&kb,  g_k);
    cudaGetSymbolAddress((void**)&vb,  g_v);
    cudaGetSymbolAddress((void**)&vt,  g_vt);
    cudaGetSymbolAddress((void**)&ab,  g_a);
    cudaGetSymbolAddress((void**)&qhh, g_qh);
    cudaGetSymbolAddress((void**)&qll, g_ql);
    cudaGetSymbolAddress((void**)&khh, g_kh);
    cudaGetSymbolAddress((void**)&kll, g_kl);
    cudaGetSymbolAddress((void**)&vth, g_vth);
    cudaGetSymbolAddress((void**)&vtl, g_vtl);

    cudaFuncSetAttribute(tgemm,   cudaFuncAttributeMaxDynamicSharedMemorySize, GSMB);
    cudaFuncSetAttribute(flash_k, cudaFuncAttributeMaxDynamicSharedMemorySize, FSMEM);

    const long HH  = (long)SEQ * HIDDEN;
    const long HDW = (long)HD * HIDDEN;
    const long SH  = (long)SEQ * HD;

    // Q/K/V projections (NT)
    tgemm<<<dim3(1, 16, NH),  256, GSMB>>>(qhid, qw, qb, HIDDEN, HIDDEN, HIDDEN, HD, HH, HDW, SH);
    tgemm<<<dim3(1, 16, NKV), 256, GSMB>>>(khid, kw, kb, HIDDEN, HIDDEN, HIDDEN, HD, HH, HDW, SH);
    tgemm<<<dim3(1, 16, NKV), 256, GSMB>>>(vhid, vw, vb, HIDDEN, HIDDEN, HIDDEN, HD, HH, HDW, SH);

    // RoPE
    rope_k<<<(NH  * SEQ * 64 + 255) / 256, 256>>>(qb, pos, NH);
    rope_k<<<(NKV * SEQ * 64 + 255) / 256, 256>>>(kb, pos, NKV);

    // V transpose, then f16 hi/lo splits for flash inputs
    transpose_v<<<dim3(64, 4, NKV), dim3(32, 8)>>>(vb, vt);
    split_k<<<(NH  * SEQ * HD) / 1024, 256>>>(qb, qhh, qll, NH  * SEQ * HD);
    split_k<<<(NKV * SEQ * HD) / 1024, 256>>>(kb, khh, kll, NKV * SEQ * HD);
    split_k<<<(NKV * HD * SEQ) / 1024, 256>>>(vt, vth, vtl, NKV * HD * SEQ);

    // fused attention -> g_a
    flash_k<<<dim3(NH, 16), 256, FSMEM>>>(qhh, qll, khh, kll, vth, vtl, ab);

    // O projection: out[l, d] = attn[l, :] . ow[d, z*128 + :]
    tgemm<<<dim3(16, 16, NH), 256, GSMB>>>(ab, ow, out, HD, HD, HIDDEN, HIDDEN, SH, (long)HD, HH);
}

// round 5
// speedup vs baseline: 3.7785x; 1.2756x over previous
#include <cuda_runtime.h>
#include <cuda_fp16.h>
#include <math.h>
#include <stdint.h>

#define SEQ     2048
#define HIDDEN  2048
#define HD      128
#define NH      16
#define NKV     2

// ---------------- scratch (device globals) ----------------
__device__ __align__(16) float  g_q [(size_t)NH  * SEQ * HD];
__device__ __align__(16) float  g_k [(size_t)NKV * SEQ * HD];
__device__ __align__(16) float  g_v [(size_t)NKV * SEQ * HD];
__device__ __align__(16) __half g_qh [(size_t)NH  * SEQ * HD];
__device__ __align__(16) __half g_ql [(size_t)NH  * SEQ * HD];
__device__ __align__(16) __half g_kh [(size_t)NKV * SEQ * HD];
__device__ __align__(16) __half g_vth[(size_t)NKV * HD * SEQ];
__device__ __align__(16) __half g_ah [(size_t)NH  * SEQ * HD];
__device__ __align__(16) __half g_al [(size_t)NH  * SEQ * HD];
// packed f16 weights: qw | kw | vw | ow
#define QW_OFF 0
#define KW_OFF 4194304
#define VW_OFF 4718592
#define OW_OFF 5242880
__device__ __align__(16) __half g_wh[9437184];

// ================= helpers =================
__device__ __forceinline__ uint32_t smem_u32(const void* p) {
    uint32_t a;
    asm("{ .reg .u64 t; cvta.to.shared.u64 t, %1; cvt.u32.u64 %0, t; }" : "=r"(a) : "l"(p));
    return a;
}

#define LDSM4(r0, r1, r2, r3, addr) \
    asm volatile("ldmatrix.sync.aligned.m8n8.x4.shared.b16 {%0,%1,%2,%3}, [%4];" \
                 : "=r"(r0), "=r"(r1), "=r"(r2), "=r"(r3) : "r"(addr))

#define MMA16816(c, a, b) \
    asm volatile("mma.sync.aligned.m16n8k16.row.col.f32.f16.f16.f32 " \
                 "{%0,%1,%2,%3}, {%4,%5,%6,%7}, {%8,%9}, {%0,%1,%2,%3};" \
                 : "+f"((c)[0]), "+f"((c)[1]), "+f"((c)[2]), "+f"((c)[3]) \
                 : "r"((a)[0]), "r"((a)[1]), "r"((a)[2]), "r"((a)[3]), \
                   "r"((b)[0]), "r"((b)[1]))

#define CPA16(dst, src) \
    asm volatile("cp.async.cg.shared.global [%0], [%1], 16;" :: "r"(dst), "l"(src))
#define CPA_COMMIT()  asm volatile("cp.async.commit_group;")
#define CPA_WAIT0()   asm volatile("cp.async.wait_group 0;")
#define CPA_WAIT1()   asm volatile("cp.async.wait_group 1;")

// ================= projection GEMM (2-term split: Ah*Bh + Al*Bh) =================
// per-buffer smem: AH [0,10240), AL [10240,20480), BH [20480,30720)
#define ROWB  80
#define TILEB (128 * ROWB)
#define BUF2  (3 * TILEB)
#define GSMB  (2 * BUF2)

__device__ __forceinline__ void cvt_split16(const float* __restrict__ xs,
                                            uint32_t* __restrict__ hw,
                                            uint32_t* __restrict__ lw)
{
#pragma unroll
    for (int q = 0; q < 8; q++) {
        float a0 = xs[2 * q], a1 = xs[2 * q + 1];
        __half2 h = __floats2half2_rn(a0, a1);
        float2 hf = __half22float2(h);
        __half2 l = __floats2half2_rn(a0 - hf.x, a1 - hf.y);
        hw[q] = *reinterpret_cast<uint32_t*>(&h);
        lw[q] = *reinterpret_cast<uint32_t*>(&l);
    }
}

// AF32: A is fp32 in gmem (cvt to hi/lo in loader). else A is pre-split f16 (cp.async).
template<bool AF32>
__global__ __launch_bounds__(256, 1)
void tgemm(const float* __restrict__ Af, const __half* __restrict__ Ahg,
           const __half* __restrict__ Alg, const __half* __restrict__ Bhg,
           float* __restrict__ Cb, int K, int lda, int ldb, int ldc,
           long sA, long sB, long sC)
{
    extern __shared__ char dsm[];
    const int tid  = threadIdx.x;
    const int wid  = tid >> 5;
    const int lane = tid & 31;
    const int wm   = (wid >> 2) << 6;
    const int wn   = (wid & 3) << 5;
    const int z    = blockIdx.z;
    const int m0   = blockIdx.y << 7;
    const int n0   = blockIdx.x << 7;

    const float*  A  = AF32 ? (Af  + (long)z * sA + (long)m0 * lda) : nullptr;
    const __half* Ah = AF32 ? nullptr : (Ahg + (long)z * sA + (long)m0 * lda);
    const __half* Al = AF32 ? nullptr : (Alg + (long)z * sA + (long)m0 * lda);
    const __half* B  = Bhg + (long)z * sB + (long)n0 * ldb;
    float*        C  = Cb + (long)z * sC;

    const int nch  = K >> 5;
    const int lrow = tid >> 1, lhalf = tid & 1;
    const int soff = lrow * ROWB + lhalf * 32;

    float acc[4][4][4];
#pragma unroll
    for (int i = 0; i < 4; i++)
#pragma unroll
        for (int j = 0; j < 4; j++)
#pragma unroll
            for (int q = 0; q < 4; q++) acc[i][j][q] = 0.f;

    const uint32_t smbase = smem_u32(dsm);
    const int a_row  = wm + (lane & 15);
    const int a_koff = (lane >> 4) << 4;
    const int b_row  = wn + (lane & 7) + ((lane >> 4) & 1) * 8;
    const int b_koff = ((lane >> 3) & 1) << 4;

    // cp.async lane mapping: row = tid>>1, two 16B units at (tid&1)*32 + {0,16}
    const uint32_t cp_off = (uint32_t)lrow * ROWB + (uint32_t)lhalf * 32;
    const long     cp_src = (long)lrow * ldb + lhalf * 16;     // halves (B)
    const long     cp_srca = (long)lrow * lda + lhalf * 16;    // halves (A16)

    float ra[16];
    // ---- prologue: chunk 0 ----
    {
        const uint32_t bb = smbase;
        CPA16(bb + 2 * TILEB + cp_off,      B + cp_src);
        CPA16(bb + 2 * TILEB + cp_off + 16, B + cp_src + 8);
        if (AF32) {
            const float4* pa = (const float4*)(A + (long)lrow * lda + lhalf * 16);
#pragma unroll
            for (int q = 0; q < 4; q++) *(float4*)(ra + 4 * q) = pa[q];
            uint32_t hw[8], lw[8];
            cvt_split16(ra, hw, lw);
            *(uint4*)(dsm + soff)              = make_uint4(hw[0], hw[1], hw[2], hw[3]);
            *(uint4*)(dsm + soff + 16)         = make_uint4(hw[4], hw[5], hw[6], hw[7]);
            *(uint4*)(dsm + TILEB + soff)      = make_uint4(lw[0], lw[1], lw[2], lw[3]);
            *(uint4*)(dsm + TILEB + soff + 16) = make_uint4(lw[4], lw[5], lw[6], lw[7]);
        } else {
            CPA16(bb + cp_off,              Ah + cp_srca);
            CPA16(bb + cp_off + 16,         Ah + cp_srca + 8);
            CPA16(bb + TILEB + cp_off,      Al + cp_srca);
            CPA16(bb + TILEB + cp_off + 16, Al + cp_srca + 8);
        }
        CPA_COMMIT();
        CPA_WAIT0();
    }
    __syncthreads();

    for (int i = 0; i < nch; i++) {
        // issue next chunk's async loads / LDGs before MMA
        if (i + 1 < nch) {
            const int k0 = (i + 1) << 5;
            const uint32_t bb = smbase + ((i + 1) & 1) * BUF2;
            CPA16(bb + 2 * TILEB + cp_off,      B + k0 + cp_src);
            CPA16(bb + 2 * TILEB + cp_off + 16, B + k0 + cp_src + 8);
            if (AF32) {
                const float4* pa = (const float4*)(A + (long)lrow * lda + k0 + lhalf * 16);
#pragma unroll
                for (int q = 0; q < 4; q++) *(float4*)(ra + 4 * q) = pa[q];
            } else {
                CPA16(bb + cp_off,              Ah + k0 + cp_srca);
                CPA16(bb + cp_off + 16,         Ah + k0 + cp_srca + 8);
                CPA16(bb + TILEB + cp_off,      Al + k0 + cp_srca);
                CPA16(bb + TILEB + cp_off + 16, Al + k0 + cp_srca + 8);
            }
            CPA_COMMIT();
        }
        // MMA on current buffer (2-term)
        const uint32_t tb = smbase + (i & 1) * BUF2;
#pragma unroll
        for (int ks = 0; ks < 2; ks++) {
            uint32_t ah[4][4], al[4][4], bh[4][2];
            const uint32_t ka = ks * 32 + a_koff;
            const uint32_t kb = ks * 32 + b_koff;
#pragma unroll
            for (int mi = 0; mi < 4; mi++) {
                LDSM4(ah[mi][0], ah[mi][1], ah[mi][2], ah[mi][3],
                      tb + (uint32_t)(a_row + mi * 16) * ROWB + ka);
                LDSM4(al[mi][0], al[mi][1], al[mi][2], al[mi][3],
                      tb + TILEB + (uint32_t)(a_row + mi * 16) * ROWB + ka);
            }
#pragma unroll
            for (int p = 0; p < 2; p++) {
                uint32_t r0, r1, r2, r3;
                LDSM4(r0, r1, r2, r3, tb + 2 * TILEB + (uint32_t)(b_row + p * 16) * ROWB + kb);
                bh[2 * p][0] = r0; bh[2 * p][1] = r1;
                bh[2 * p + 1][0] = r2; bh[2 * p + 1][1] = r3;
            }
#pragma unroll
            for (int mi = 0; mi < 4; mi++)
#pragma unroll
                for (int ni = 0; ni < 4; ni++) {
                    MMA16816(acc[mi][ni], ah[mi], bh[ni]);
                    MMA16816(acc[mi][ni], al[mi], bh[ni]);
                }
        }
        // store next A chunk (fp32 path)
        if (i + 1 < nch) {
            if (AF32) {
                char* buf = dsm + ((i + 1) & 1) * BUF2;
                uint32_t hw[8], lw[8];
                cvt_split16(ra, hw, lw);
                *(uint4*)(buf + soff)              = make_uint4(hw[0], hw[1], hw[2], hw[3]);
                *(uint4*)(buf + soff + 16)         = make_uint4(hw[4], hw[5], hw[6], hw[7]);
                *(uint4*)(buf + TILEB + soff)      = make_uint4(lw[0], lw[1], lw[2], lw[3]);
                *(uint4*)(buf + TILEB + soff + 16) = make_uint4(lw[4], lw[5], lw[6], lw[7]);
            }
            CPA_WAIT0();
        }
        __syncthreads();
    }

    // epilogue
    const int g = lane >> 2, t = lane & 3;
#pragma unroll
    for (int mi = 0; mi < 4; mi++) {
        const int r0 = m0 + wm + mi * 16 + g;
#pragma unroll
        for (int ni = 0; ni < 4; ni++) {
            const int cc = n0 + wn + ni * 8 + t * 2;
            *(float2*)(C + (long)r0 * ldc + cc)       = make_float2(acc[mi][ni][0], acc[mi][ni][1]);
            *(float2*)(C + (long)(r0 + 8) * ldc + cc) = make_float2(acc[mi][ni][2], acc[mi][ni][3]);
        }
    }
}

// ================= flash attention (2-term: Q hi/lo x K hi; P hi/lo x V hi) =================
// smem: QH [0,34816), QL [34816,69632), K bufs [69632,+17408x2), VT bufs [104448,+18432x2)
#define QL_OFF 34816
#define K_OFF  69632
#define KBUFB  17408
#define V_OFF  104448
#define VBUFB  18432
#define FSMEM  141312
#define FC     0.12751744f   // log2(e) / sqrt(128)

__device__ __forceinline__ void kv_prefetch(uint32_t smb, int buf, int kv0,
    const __half* __restrict__ khp, const __half* __restrict__ vhp, int tid)
{
#pragma unroll
    for (int i = 0; i < 4; i++) {
        int t = tid + (i << 8);
        int unit = t & 15, row = t >> 4;            // row 0..63
        const __half* src = khp + (long)(kv0 + row) * HD + unit * 8;
        CPA16(smb + K_OFF + buf * KBUFB + row * 272 + unit * 16, src);
    }
#pragma unroll
    for (int i = 0; i < 4; i++) {
        int t = tid + (i << 8);
        int unit = t & 7, row = t >> 3;             // row 0..127
        const __half* src = vhp + (long)row * SEQ + kv0 + unit * 8;
        CPA16(smb + V_OFF + buf * VBUFB + row * 144 + unit * 16, src);
    }
}

__global__ __launch_bounds__(256, 1)
void flash_k(const __half* __restrict__ qhg, const __half* __restrict__ qlg,
             const __half* __restrict__ khg, const __half* __restrict__ vhg,
             __half* __restrict__ oah, __half* __restrict__ oal)
{
    extern __shared__ char dsm[];
    const uint32_t smb = smem_u32(dsm);
    const int tid  = threadIdx.x;
    const int w    = tid >> 5;
    const int lane = tid & 31;
    const int z    = blockIdx.x;
    const int mb   = 15 - blockIdx.y;     // heavy blocks first
    const int kvh  = z >> 3;
    const int m0   = mb << 7;
    const int nt   = (mb + 1) << 1;

    const __half* qhp = qhg + ((long)z * SEQ + m0) * HD;
    const __half* qlp = qlg + ((long)z * SEQ + m0) * HD;
    const __half* khp = khg + (long)kvh * SEQ * HD;
    const __half* vhp = vhg + (long)kvh * HD * SEQ;

    // Q hi/lo -> smem (one-time)
#pragma unroll
    for (int i = 0; i < 16; i++) {
        int t = tid + (i << 8);
        int unit = t & 15, row = (t >> 4) & 127, hl = t >> 11;
        const __half* src = (hl ? qlp : qhp) + (long)row * HD + unit * 8;
        CPA16(smb + hl * QL_OFF + row * 272 + unit * 16, src);
    }
    CPA_COMMIT();
    kv_prefetch(smb, 0, 0, khp, vhp, tid);
    CPA_COMMIT();

    float o[16][4];
#pragma unroll
    for (int nb = 0; nb < 16; nb++)
#pragma unroll
        for (int q = 0; q < 4; q++) o[nb][q] = 0.f;
    float mr0 = -1e30f, mr1 = -1e30f, l0 = 0.f, l1 = 0.f;

    const int wrow = m0 + (w << 4);
    const uint32_t qa_h = smb + (uint32_t)((w << 4) + (lane & 15)) * 272 + ((lane >> 4) << 4);
    const uint32_t qa_l = qa_h + QL_OFF;
    const uint32_t brow = (lane & 7) + ((lane >> 4) & 1) * 8;
    const uint32_t bko  = ((lane >> 3) & 1) << 4;

    int buf = 0;
    for (int it = 0; it < nt; it++) {
        if (it + 1 < nt) {
            kv_prefetch(smb, buf ^ 1, (it + 1) << 6, khp, vhp, tid);
            CPA_COMMIT();
            CPA_WAIT1();
        } else {
            CPA_WAIT0();
        }
        __syncthreads();

        const int kv0 = it << 6;
        if (kv0 <= wrow + 15) {
            const uint32_t kb_h = smb + K_OFF + buf * KBUFB;
            const uint32_t vb_h = smb + V_OFF + buf * VBUFB;

            float s[8][4];
#pragma unroll
            for (int nb = 0; nb < 8; nb++)
#pragma unroll
                for (int q = 0; q < 4; q++) s[nb][q] = 0.f;

            // ---- scores: s = Q . K^T (Qh*Kh + Ql*Kh) ----
#pragma unroll
            for (int j = 0; j < 8; j++) {
                uint32_t ah[4], al[4];
                LDSM4(ah[0], ah[1], ah[2], ah[3], qa_h + j * 32);
                LDSM4(al[0], al[1], al[2], al[3], qa_l + j * 32);
#pragma unroll
                for (int g16 = 0; g16 < 4; g16++) {
                    uint32_t bh[4];
                    const uint32_t ba = (uint32_t)(g16 * 16 + brow) * 272 + bko + j * 32;
                    LDSM4(bh[0], bh[1], bh[2], bh[3], kb_h + ba);
                    MMA16816(s[2 * g16],     ah, bh);
                    MMA16816(s[2 * g16],     al, bh);
                    MMA16816(s[2 * g16 + 1], ah, bh + 2);
                    MMA16816(s[2 * g16 + 1], al, bh + 2);
                }
            }

            // ---- causal mask ----
            const int r0 = wrow + (lane >> 2);
            const int c0 = kv0 + ((lane & 3) << 1);
            if (kv0 + 63 > wrow) {
#pragma unroll
                for (int nb = 0; nb < 8; nb++) {
                    const int c = c0 + nb * 8;
                    if (c     > r0    ) s[nb][0] = -1e30f;
                    if (c + 1 > r0    ) s[nb][1] = -1e30f;
                    if (c     > r0 + 8) s[nb][2] = -1e30f;
                    if (c + 1 > r0 + 8) s[nb][3] = -1e30f;
                }
            }

            // ---- online softmax ----
            float tm0 = -1e30f, tm1 = -1e30f;
#pragma unroll
            for (int nb = 0; nb < 8; nb++) {
                tm0 = fmaxf(tm0, fmaxf(s[nb][0], s[nb][1]));
                tm1 = fmaxf(tm1, fmaxf(s[nb][2], s[nb][3]));
            }
            tm0 = fmaxf(tm0, __shfl_xor_sync(0xffffffffu, tm0, 1));
            tm0 = fmaxf(tm0, __shfl_xor_sync(0xffffffffu, tm0, 2));
            tm1 = fmaxf(tm1, __shfl_xor_sync(0xffffffffu, tm1, 1));
            tm1 = fmaxf(tm1, __shfl_xor_sync(0xffffffffu, tm1, 2));
            const float mn0 = fmaxf(mr0, tm0), mn1 = fmaxf(mr1, tm1);
            const float sf0 = exp2f((mr0 - mn0) * FC);
            const float sf1 = exp2f((mr1 - mn1) * FC);
            mr0 = mn0; mr1 = mn1;
            l0 *= sf0;  l1 *= sf1;
#pragma unroll
            for (int nb = 0; nb < 16; nb++) {
                o[nb][0] *= sf0; o[nb][1] *= sf0;
                o[nb][2] *= sf1; o[nb][3] *= sf1;
            }
            float rs0 = 0.f, rs1 = 0.f;
#pragma unroll
            for (int nb = 0; nb < 8; nb++) {
                s[nb][0] = exp2f((s[nb][0] - mn0) * FC); rs0 += s[nb][0];
                s[nb][1] = exp2f((s[nb][1] - mn0) * FC); rs0 += s[nb][1];
                s[nb][2] = exp2f((s[nb][2] - mn1) * FC); rs1 += s[nb][2];
                s[nb][3] = exp2f((s[nb][3] - mn1) * FC); rs1 += s[nb][3];
            }
            rs0 += __shfl_xor_sync(0xffffffffu, rs0, 1);
            rs0 += __shfl_xor_sync(0xffffffffu, rs0, 2);
            rs1 += __shfl_xor_sync(0xffffffffu, rs1, 1);
            rs1 += __shfl_xor_sync(0xffffffffu, rs1, 2);
            l0 += rs0; l1 += rs1;

            // ---- PV: o += P . V (Ph*Vh + Pl*Vh) ----
#pragma unroll
            for (int j = 0; j < 4; j++) {
                uint32_t pha[4], pla[4];
#pragma unroll
                for (int hq = 0; hq < 4; hq++) {
                    const int nb = 2 * j + (hq >> 1);
                    const int e  = (hq & 1) << 1;
                    const float p0 = s[nb][e], p1 = s[nb][e + 1];
                    __half2 h = __floats2half2_rn(p0, p1);
                    float2 hf = __half22float2(h);
                    __half2 l = __floats2half2_rn(p0 - hf.x, p1 - hf.y);
                    pha[hq] = *reinterpret_cast<uint32_t*>(&h);
                    pla[hq] = *reinterpret_cast<uint32_t*>(&l);
                }
#pragma unroll
                for (int g16 = 0; g16 < 8; g16++) {
                    uint32_t bh[4];
                    const uint32_t ba = (uint32_t)(g16 * 16 + brow) * 144 + bko + j * 32;
                    LDSM4(bh[0], bh[1], bh[2], bh[3], vb_h + ba);
                    MMA16816(o[2 * g16],     pha, bh);
                    MMA16816(o[2 * g16],     pla, bh);
                    MMA16816(o[2 * g16 + 1], pha, bh + 2);
                    MMA16816(o[2 * g16 + 1], pla, bh + 2);
                }
            }
        }
        __syncthreads();
        buf ^= 1;
    }

    // ---- epilogue: normalize, split to f16 hi/lo, write ----
    const float inv0 = 1.f / l0, inv1 = 1.f / l1;
    const int r0 = wrow + (lane >> 2);
    const long base0 = ((long)z * SEQ + r0) * HD + ((lane & 3) << 1);
    const long base1 = base0 + 8 * HD;
#pragma unroll
    for (int nb = 0; nb < 16; nb++) {
        float f0 = o[nb][0] * inv0, f1 = o[nb][1] * inv0;
        __half2 h = __floats2half2_rn(f0, f1);
        float2 hf = __half22float2(h);
        __half2 l = __floats2half2_rn(f0 - hf.x, f1 - hf.y);
        *(__half2*)(oah + base0 + nb * 8) = h;
        *(__half2*)(oal + base0 + nb * 8) = l;
        float f2 = o[nb][2] * inv1, f3 = o[nb][3] * inv1;
        h = __floats2half2_rn(f2, f3);
        hf = __half22float2(h);
        l = __floats2half2_rn(f2 - hf.x, f3 - hf.y);
        *(__half2*)(oah + base1 + nb * 8) = h;
        *(__half2*)(oal + base1 + nb * 8) = l;
    }
}

// ---------------- RoPE: fp32 in, f16 hi(/lo) out ----------------
template<bool WLO>
__global__ __launch_bounds__(256)
void rope_k(const float* __restrict__ buf, __half* __restrict__ dh,
            __half* __restrict__ dl, const int* __restrict__ pos, int heads)
{
    int idx = blockIdx.x * 256 + threadIdx.x;
    int total = heads * SEQ * 64;
    if (idx >= total) return;
    int i = idx & 63;
    int l = (idx >> 6) % SEQ;
    int n = idx / (SEQ * 64);

    float invf = exp2f(-(float)i * 0.31143075889569023f);
    float ang  = (float)pos[l] * invf;
    float q  = rintf(ang * 0.15915494309189535f);
    float r  = ang - q * 6.28125f;
    r        = r   - q * 1.9353071795864769e-3f;
    float s, c;
    sincosf(r, &s, &c);

    const long base = ((long)n * SEQ + l) * HD;
    const float x1 = buf[base + i], x2 = buf[base + i + 64];
    const float y1 = x1 * c - x2 * s;
    const float y2 = x2 * c + x1 * s;
    const __half h1 = __float2half_rn(y1);
    const __half h2 = __float2half_rn(y2);
    dh[base + i]      = h1;
    dh[base + i + 64] = h2;
    if (WLO) {
        dl[base + i]      = __float2half_rn(y1 - __half2float(h1));
        dl[base + i + 64] = __float2half_rn(y2 - __half2float(h2));
    }
}

// ---------------- V transpose: fp32 [kv][S][128] -> f16 [kv][128][S] ----------------
__global__ __launch_bounds__(256)
void transpose_vh(const float* __restrict__ v, __half* __restrict__ vt)
{
    __shared__ float t[32][33];
    int h  = blockIdx.z;
    int s0 = blockIdx.x * 32, d0 = blockIdx.y * 32;
    const float* src = v + ((long)h * SEQ + s0) * HD + d0;
#pragma unroll
    for (int yy = threadIdx.y; yy < 32; yy += 8)
        t[yy][threadIdx.x] = src[yy * HD + threadIdx.x];
    __syncthreads();
    __half* dst = vt + ((long)h * HD + d0) * SEQ + s0;
#pragma unroll
    for (int yy = threadIdx.y; yy < 32; yy += 8)
        dst[(long)yy * SEQ + threadIdx.x] = __float2half_rn(t[threadIdx.x][yy]);
}

// ---------------- fp32 -> f16 weight rounding ----------------
__global__ __launch_bounds__(256)
void cvt16_k(const float* __restrict__ s, __half* __restrict__ d, int n)
{
    int i = (blockIdx.x * 256 + threadIdx.x) << 2;
    if (i >= n) return;
    float4 v = *(const float4*)(s + i);
    ((__half2*)(d + i))[0] = __floats2half2_rn(v.x, v.y);
    ((__half2*)(d + i))[1] = __floats2half2_rn(v.z, v.w);
}

// ---------------- launch ----------------
extern "C" void kernel_launch(void* const* d_in, const int* in_sizes, int n_in,
                              void* d_out, int out_size)
{
    const float* qhid = (const float*)d_in[0];
    const float* khid = (const float*)d_in[1];
    const float* vhid = (const float*)d_in[2];
    const int*   pos  = (const int*)  d_in[4];
    const float* qw   = (const float*)d_in[5];
    const float* kw   = (const float*)d_in[6];
    const float* vw   = (const float*)d_in[7];
    const float* ow   = (const float*)d_in[8];
    float*       out  = (float*)d_out;

    float *qb, *kb, *vb;
    __half *qhh, *qll, *khh, *vth, *ahh, *all, *wh;
    cudaGetSymbolAddress((void**)&qb,  g_q);
    cudaGetSymbolAddress((void**)&kb,  g_k);
    cudaGetSymbolAddress((void**)&vb,  g_v);
    cudaGetSymbolAddress((void**)&qhh, g_qh);
    cudaGetSymbolAddress((void**)&qll, g_ql);
    cudaGetSymbolAddress((void**)&khh, g_kh);
    cudaGetSymbolAddress((void**)&vth, g_vth);
    cudaGetSymbolAddress((void**)&ahh, g_ah);
    cudaGetSymbolAddress((void**)&all, g_al);
    cudaGetSymbolAddress((void**)&wh,  g_wh);

    cudaFuncSetAttribute(tgemm<true>,  cudaFuncAttributeMaxDynamicSharedMemorySize, GSMB);
    cudaFuncSetAttribute(tgemm<false>, cudaFuncAttributeMaxDynamicSharedMemorySize, GSMB);
    cudaFuncSetAttribute(flash_k,      cudaFuncAttributeMaxDynamicSharedMemorySize, FSMEM);

    const long HH  = (long)SEQ * HIDDEN;
    const long HDW = (long)HD * HIDDEN;
    const long SH  = (long)SEQ * HD;

    // weights -> f16
    cvt16_k<<<(HIDDEN * HIDDEN) / 1024, 256>>>(qw, wh + QW_OFF, HIDDEN * HIDDEN);
    cvt16_k<<<(256 * HIDDEN)    / 1024, 256>>>(kw, wh + KW_OFF, 256 * HIDDEN);
    cvt16_k<<<(256 * HIDDEN)    / 1024, 256>>>(vw, wh + VW_OFF, 256 * HIDDEN);
    cvt16_k<<<(HIDDEN * HIDDEN) / 1024, 256>>>(ow, wh + OW_OFF, HIDDEN * HIDDEN);

    // Q/K/V projections (NT): A fp32 hidden, B f16 weights
    tgemm<true><<<dim3(1, 16, NH),  256, GSMB>>>(qhid, nullptr, nullptr, wh + QW_OFF,
        qb, HIDDEN, HIDDEN, HIDDEN, HD, HH, HDW, SH);
    tgemm<true><<<dim3(1, 16, NKV), 256, GSMB>>>(khid, nullptr, nullptr, wh + KW_OFF,
        kb, HIDDEN, HIDDEN, HIDDEN, HD, HH, HDW, SH);
    tgemm<true><<<dim3(1, 16, NKV), 256, GSMB>>>(vhid, nullptr, nullptr, wh + VW_OFF,
        vb, HIDDEN, HIDDEN, HIDDEN, HD, HH, HDW, SH);

    // RoPE -> f16 (q: hi+lo, k: hi only)
    rope_k<true ><<<(NH  * SEQ * 64 + 255) / 256, 256>>>(qb, qhh, qll, pos, NH);
    rope_k<false><<<(NKV * SEQ * 64 + 255) / 256, 256>>>(kb, khh, nullptr, pos, NKV);

    // V transpose -> f16 hi
    transpose_vh<<<dim3(64, 4, NKV), dim3(32, 8)>>>(vb, vth);

    // fused attention -> attn f16 hi/lo
    flash_k<<<dim3(NH, 16), 256, FSMEM>>>(qhh, qll, khh, vth, ahh, all);

    // O projection: A = attn (f16 hi/lo), B = ow f16 (per-head column offset z*128)
    tgemm<false><<<dim3(16, 16, NH), 256, GSMB>>>(nullptr, ahh, all, wh + OW_OFF,
        out, HD, HD, HIDDEN, HIDDEN, SH, (long)HD, HH);
}

// round 6
// speedup vs baseline: 5.4080x; 1.4313x over previous
#include <cuda_runtime.h>
#include <cuda_fp16.h>
#include <math.h>
#include <stdint.h>

#define SEQ     2048
#define HIDDEN  2048
#define HD      128
#define NH      16
#define NKV     2

// ---------------- scratch (device globals) ----------------
__device__ __align__(16) float  g_q [(size_t)NH  * SEQ * HD];
__device__ __align__(16) float  g_k [(size_t)NKV * SEQ * HD];
__device__ __align__(16) float  g_v [(size_t)NKV * SEQ * HD];
__device__ __align__(16) __half g_qh [(size_t)NH  * SEQ * HD];
__device__ __align__(16) __half g_ql [(size_t)NH  * SEQ * HD];
__device__ __align__(16) __half g_kh [(size_t)NKV * SEQ * HD];
__device__ __align__(16) __half g_vth[(size_t)NKV * HD * SEQ];
__device__ __align__(16) __half g_ah [(size_t)NH  * SEQ * HD];
// packed f16 weights: qw | kw | vw | ow
#define QW_OFF 0
#define KW_OFF 4194304
#define VW_OFF 4718592
#define OW_OFF 5242880
__device__ __align__(16) __half g_wh[9437184];

// ================= helpers =================
__device__ __forceinline__ uint32_t smem_u32(const void* p) {
    uint32_t a;
    asm("{ .reg .u64 t; cvta.to.shared.u64 t, %1; cvt.u32.u64 %0, t; }" : "=r"(a) : "l"(p));
    return a;
}

#define LDSM4(r0, r1, r2, r3, addr) \
    asm volatile("ldmatrix.sync.aligned.m8n8.x4.shared.b16 {%0,%1,%2,%3}, [%4];" \
                 : "=r"(r0), "=r"(r1), "=r"(r2), "=r"(r3) : "r"(addr))

#define MMA16816(c, a, b) \
    asm volatile("mma.sync.aligned.m16n8k16.row.col.f32.f16.f16.f32 " \
                 "{%0,%1,%2,%3}, {%4,%5,%6,%7}, {%8,%9}, {%0,%1,%2,%3};" \
                 : "+f"((c)[0]), "+f"((c)[1]), "+f"((c)[2]), "+f"((c)[3]) \
                 : "r"((a)[0]), "r"((a)[1]), "r"((a)[2]), "r"((a)[3]), \
                   "r"((b)[0]), "r"((b)[1]))

#define CPA16(dst, src) \
    asm volatile("cp.async.cg.shared.global [%0], [%1], 16;" :: "r"(dst), "l"(src))
#define CPA_COMMIT()  asm volatile("cp.async.commit_group;")
#define CPA_WAIT0()   asm volatile("cp.async.wait_group 0;")
#define CPA_WAIT1()   asm volatile("cp.async.wait_group 1;")

// ================= projection GEMM =================
// per-buffer smem: AH [0,10240), AL [10240,20480), BH [20480,30720)
#define ROWB  80
#define TILEB (128 * ROWB)
#define BUF2  (3 * TILEB)
#define GSMB  (2 * BUF2)

__device__ __forceinline__ void cvt_split16(const float* __restrict__ xs,
                                            uint32_t* __restrict__ hw,
                                            uint32_t* __restrict__ lw)
{
#pragma unroll
    for (int q = 0; q < 8; q++) {
        float a0 = xs[2 * q], a1 = xs[2 * q + 1];
        __half2 h = __floats2half2_rn(a0, a1);
        float2 hf = __half22float2(h);
        __half2 l = __floats2half2_rn(a0 - hf.x, a1 - hf.y);
        hw[q] = *reinterpret_cast<uint32_t*>(&h);
        lw[q] = *reinterpret_cast<uint32_t*>(&l);
    }
}

// AF32: A fp32 in gmem, cvt->hi/lo f16 in loader, 2-term MMA.
// !AF32: A f16 in gmem via cp.async; SPLIT selects 2-term vs 1-term.
// Dual pointer sets + zsplit: z >= zsplit switches to the second problem (merged K+V launch).
template<bool AF32, bool SPLIT>
__global__ __launch_bounds__(256, 2)
void tgemm(const float* __restrict__ Af, const __half* __restrict__ Ahg,
           const __half* __restrict__ Bhg, float* __restrict__ Cb,
           const float* __restrict__ Af2, const __half* __restrict__ Bhg2,
           float* __restrict__ Cb2, int zsplit,
           int K, int lda, int ldb, int ldc, long sA, long sB, long sC)
{
    extern __shared__ char dsm[];
    const int tid  = threadIdx.x;
    const int wid  = tid >> 5;
    const int lane = tid & 31;
    const int wm   = (wid >> 2) << 6;
    const int wn   = (wid & 3) << 5;
    int z          = blockIdx.z;
    const int m0   = blockIdx.y << 7;
    const int n0   = blockIdx.x << 7;

    const float*  Afz = Af;
    const __half* Bz  = Bhg;
    float*        Cz  = Cb;
    if (z >= zsplit) { Afz = Af2; Bz = Bhg2; Cz = Cb2; z -= zsplit; }

    const float*  A  = AF32 ? (Afz + (long)z * sA + (long)m0 * lda) : nullptr;
    const __half* Ah = AF32 ? nullptr : (Ahg + (long)z * sA + (long)m0 * lda);
    const __half* B  = Bz + (long)z * sB + (long)n0 * ldb;
    float*        C  = Cz + (long)z * sC;

    const int nch  = K >> 5;
    const int lrow = tid >> 1, lhalf = tid & 1;
    const int soff = lrow * ROWB + lhalf * 32;

    float acc[4][4][4];
#pragma unroll
    for (int i = 0; i < 4; i++)
#pragma unroll
        for (int j = 0; j < 4; j++)
#pragma unroll
            for (int q = 0; q < 4; q++) acc[i][j][q] = 0.f;

    const uint32_t smbase = smem_u32(dsm);
    const int a_row  = wm + (lane & 15);
    const int a_koff = (lane >> 4) << 4;
    const int b_row  = wn + (lane & 7) + ((lane >> 4) & 1) * 8;
    const int b_koff = ((lane >> 3) & 1) << 4;

    const uint32_t cp_off  = (uint32_t)lrow * ROWB + (uint32_t)lhalf * 32;
    const long     cp_srcb = (long)lrow * ldb + lhalf * 16;
    const long     cp_srca = (long)lrow * lda + lhalf * 16;

    float ra[16];
    // ---- prologue: chunk 0 ----
    {
        const uint32_t bb = smbase;
        CPA16(bb + 2 * TILEB + cp_off,      B + cp_srcb);
        CPA16(bb + 2 * TILEB + cp_off + 16, B + cp_srcb + 8);
        if (AF32) {
            const float4* pa = (const float4*)(A + (long)lrow * lda + lhalf * 16);
#pragma unroll
            for (int q = 0; q < 4; q++) *(float4*)(ra + 4 * q) = pa[q];
            uint32_t hw[8], lw[8];
            cvt_split16(ra, hw, lw);
            *(uint4*)(dsm + soff)              = make_uint4(hw[0], hw[1], hw[2], hw[3]);
            *(uint4*)(dsm + soff + 16)         = make_uint4(hw[4], hw[5], hw[6], hw[7]);
            *(uint4*)(dsm + TILEB + soff)      = make_uint4(lw[0], lw[1], lw[2], lw[3]);
            *(uint4*)(dsm + TILEB + soff + 16) = make_uint4(lw[4], lw[5], lw[6], lw[7]);
        } else {
            CPA16(bb + cp_off,      Ah + cp_srca);
            CPA16(bb + cp_off + 16, Ah + cp_srca + 8);
        }
        CPA_COMMIT();
        CPA_WAIT0();
    }
    __syncthreads();

    for (int i = 0; i < nch; i++) {
        // issue next chunk's loads before MMA
        if (i + 1 < nch) {
            const int k0 = (i + 1) << 5;
            const uint32_t bb = smbase + ((i + 1) & 1) * BUF2;
            CPA16(bb + 2 * TILEB + cp_off,      B + k0 + cp_srcb);
            CPA16(bb + 2 * TILEB + cp_off + 16, B + k0 + cp_srcb + 8);
            if (AF32) {
                const float4* pa = (const float4*)(A + (long)lrow * lda + k0 + lhalf * 16);
#pragma unroll
                for (int q = 0; q < 4; q++) *(float4*)(ra + 4 * q) = pa[q];
            } else {
                CPA16(bb + cp_off,      Ah + k0 + cp_srca);
                CPA16(bb + cp_off + 16, Ah + k0 + cp_srca + 8);
            }
            CPA_COMMIT();
        }
        // MMA on current buffer (B frags held, A frags per-mi to cap regs)
        const uint32_t tb = smbase + (i & 1) * BUF2;
#pragma unroll
        for (int ks = 0; ks < 2; ks++) {
            uint32_t bh[4][2];
            const uint32_t ka = ks * 32 + a_koff;
            const uint32_t kb = ks * 32 + b_koff;
#pragma unroll
            for (int p = 0; p < 2; p++) {
                uint32_t r0, r1, r2, r3;
                LDSM4(r0, r1, r2, r3, tb + 2 * TILEB + (uint32_t)(b_row + p * 16) * ROWB + kb);
                bh[2 * p][0] = r0; bh[2 * p][1] = r1;
                bh[2 * p + 1][0] = r2; bh[2 * p + 1][1] = r3;
            }
#pragma unroll
            for (int mi = 0; mi < 4; mi++) {
                uint32_t ah[4];
                LDSM4(ah[0], ah[1], ah[2], ah[3],
                      tb + (uint32_t)(a_row + mi * 16) * ROWB + ka);
#pragma unroll
                for (int ni = 0; ni < 4; ni++) MMA16816(acc[mi][ni], ah, bh[ni]);
                if (SPLIT) {
                    uint32_t al[4];
                    LDSM4(al[0], al[1], al[2], al[3],
                          tb + TILEB + (uint32_t)(a_row + mi * 16) * ROWB + ka);
#pragma unroll
                    for (int ni = 0; ni < 4; ni++) MMA16816(acc[mi][ni], al, bh[ni]);
                }
            }
        }
        // store next A chunk (fp32 path)
        if (i + 1 < nch) {
            if (AF32) {
                char* buf = dsm + ((i + 1) & 1) * BUF2;
                uint32_t hw[8], lw[8];
                cvt_split16(ra, hw, lw);
                *(uint4*)(buf + soff)              = make_uint4(hw[0], hw[1], hw[2], hw[3]);
                *(uint4*)(buf + soff + 16)         = make_uint4(hw[4], hw[5], hw[6], hw[7]);
                *(uint4*)(buf + TILEB + soff)      = make_uint4(lw[0], lw[1], lw[2], lw[3]);
                *(uint4*)(buf + TILEB + soff + 16) = make_uint4(lw[4], lw[5], lw[6], lw[7]);
            }
            CPA_WAIT0();
        }
        __syncthreads();
    }

    // epilogue
    const int g = lane >> 2, t = lane & 3;
#pragma unroll
    for (int mi = 0; mi < 4; mi++) {
        const int r0 = m0 + wm + mi * 16 + g;
#pragma unroll
        for (int ni = 0; ni < 4; ni++) {
            const int cc = n0 + wn + ni * 8 + t * 2;
            *(float2*)(C + (long)r0 * ldc + cc)       = make_float2(acc[mi][ni][0], acc[mi][ni][1]);
            *(float2*)(C + (long)(r0 + 8) * ldc + cc) = make_float2(acc[mi][ni][2], acc[mi][ni][3]);
        }
    }
}

// ================= flash attention: 64 Q rows / CTA, 128 threads, 2 CTAs/SM =================
// smem: QH [0,17408), QL [17408,34816), K bufs [34816,+17408x2), VT bufs [69632,+18432x2)
#define QL_OFF 17408
#define K_OFF  34816
#define KBUFB  17408
#define V_OFF  69632
#define VBUFB  18432
#define FSMEM  106496
#define FC     0.12751744f   // log2(e) / sqrt(128)

__device__ __forceinline__ void kv_prefetch(uint32_t smb, int buf, int kv0,
    const __half* __restrict__ khp, const __half* __restrict__ vhp, int tid)
{
#pragma unroll
    for (int i = 0; i < 8; i++) {
        int t = tid + (i << 7);
        int unit = t & 15, row = t >> 4;            // 0..63
        CPA16(smb + K_OFF + buf * KBUFB + row * 272 + unit * 16,
              khp + (long)(kv0 + row) * HD + unit * 8);
    }
#pragma unroll
    for (int i = 0; i < 8; i++) {
        int t = tid + (i << 7);
        int unit = t & 7, row = t >> 3;             // 0..127
        CPA16(smb + V_OFF + buf * VBUFB + row * 144 + unit * 16,
              vhp + (long)row * SEQ + kv0 + unit * 8);
    }
}

__global__ __launch_bounds__(128)
void flash_k(const __half* __restrict__ qhg, const __half* __restrict__ qlg,
             const __half* __restrict__ khg, const __half* __restrict__ vhg,
             __half* __restrict__ oah)
{
    extern __shared__ char dsm[];
    const uint32_t smb = smem_u32(dsm);
    const int tid  = threadIdx.x;
    const int w    = tid >> 5;
    const int lane = tid & 31;
    const int z    = blockIdx.x;
    const int mb   = 31 - blockIdx.y;     // heavy blocks first
    const int kvh  = z >> 3;
    const int m0   = mb << 6;
    const int nt   = mb + 1;

    const __half* qhp = qhg + ((long)z * SEQ + m0) * HD;
    const __half* qlp = qlg + ((long)z * SEQ + m0) * HD;
    const __half* khp = khg + (long)kvh * SEQ * HD;
    const __half* vhp = vhg + (long)kvh * HD * SEQ;

    // Q hi/lo -> smem (one-time): 64 rows x 128 f16 x2 = 2048 16B units
#pragma unroll
    for (int i = 0; i < 16; i++) {
        int t = tid + (i << 7);
        int unit = t & 15, row = (t >> 4) & 63, hl = t >> 10;
        CPA16(smb + hl * QL_OFF + row * 272 + unit * 16,
              (hl ? qlp : qhp) + (long)row * HD + unit * 8);
    }
    CPA_COMMIT();
    kv_prefetch(smb, 0, 0, khp, vhp, tid);
    CPA_COMMIT();

    float o[16][4];
#pragma unroll
    for (int nb = 0; nb < 16; nb++)
#pragma unroll
        for (int q = 0; q < 4; q++) o[nb][q] = 0.f;
    float mr0 = -1e30f, mr1 = -1e30f, l0 = 0.f, l1 = 0.f;

    const int wrow = m0 + (w << 4);
    const uint32_t qa_h = smb + (uint32_t)((w << 4) + (lane & 15)) * 272 + ((lane >> 4) << 4);
    const uint32_t qa_l = qa_h + QL_OFF;
    const uint32_t brow = (lane & 7) + ((lane >> 4) & 1) * 8;
    const uint32_t bko  = ((lane >> 3) & 1) << 4;

    int buf = 0;
    for (int it = 0; it < nt; it++) {
        if (it + 1 < nt) {
            kv_prefetch(smb, buf ^ 1, (it + 1) << 6, khp, vhp, tid);
            CPA_COMMIT();
            CPA_WAIT1();
        } else {
            CPA_WAIT0();
        }
        __syncthreads();

        const int kv0 = it << 6;
        {
            const uint32_t kb_h = smb + K_OFF + buf * KBUFB;
            const uint32_t vb_h = smb + V_OFF + buf * VBUFB;

            float s[8][4];
#pragma unroll
            for (int nb = 0; nb < 8; nb++)
#pragma unroll
                for (int q = 0; q < 4; q++) s[nb][q] = 0.f;

            // ---- scores: s = Q . K^T (Qh*Kh + Ql*Kh) ----
#pragma unroll
            for (int j = 0; j < 8; j++) {
                uint32_t ah[4], al[4];
                LDSM4(ah[0], ah[1], ah[2], ah[3], qa_h + j * 32);
                LDSM4(al[0], al[1], al[2], al[3], qa_l + j * 32);
#pragma unroll
                for (int g16 = 0; g16 < 4; g16++) {
                    uint32_t bh[4];
                    const uint32_t ba = (uint32_t)(g16 * 16 + brow) * 272 + bko + j * 32;
                    LDSM4(bh[0], bh[1], bh[2], bh[3], kb_h + ba);
                    MMA16816(s[2 * g16],     ah, bh);
                    MMA16816(s[2 * g16],     al, bh);
                    MMA16816(s[2 * g16 + 1], ah, bh + 2);
                    MMA16816(s[2 * g16 + 1], al, bh + 2);
                }
            }

            // ---- causal mask ----
            const int r0 = wrow + (lane >> 2);
            const int c0 = kv0 + ((lane & 3) << 1);
            if (kv0 + 63 > wrow) {
#pragma unroll
                for (int nb = 0; nb < 8; nb++) {
                    const int c = c0 + nb * 8;
                    if (c     > r0    ) s[nb][0] = -1e30f;
                    if (c + 1 > r0    ) s[nb][1] = -1e30f;
                    if (c     > r0 + 8) s[nb][2] = -1e30f;
                    if (c + 1 > r0 + 8) s[nb][3] = -1e30f;
                }
            }

            // ---- online softmax ----
            float tm0 = -1e30f, tm1 = -1e30f;
#pragma unroll
            for (int nb = 0; nb < 8; nb++) {
                tm0 = fmaxf(tm0, fmaxf(s[nb][0], s[nb][1]));
                tm1 = fmaxf(tm1, fmaxf(s[nb][2], s[nb][3]));
            }
            tm0 = fmaxf(tm0, __shfl_xor_sync(0xffffffffu, tm0, 1));
            tm0 = fmaxf(tm0, __shfl_xor_sync(0xffffffffu, tm0, 2));
            tm1 = fmaxf(tm1, __shfl_xor_sync(0xffffffffu, tm1, 1));
            tm1 = fmaxf(tm1, __shfl_xor_sync(0xffffffffu, tm1, 2));
            const float mn0 = fmaxf(mr0, tm0), mn1 = fmaxf(mr1, tm1);
            const float sf0 = exp2f((mr0 - mn0) * FC);
            const float sf1 = exp2f((mr1 - mn1) * FC);
            mr0 = mn0; mr1 = mn1;
            l0 *= sf0;  l1 *= sf1;
#pragma unroll
            for (int nb = 0; nb < 16; nb++) {
                o[nb][0] *= sf0; o[nb][1] *= sf0;
                o[nb][2] *= sf1; o[nb][3] *= sf1;
            }
            float rs0 = 0.f, rs1 = 0.f;
#pragma unroll
            for (int nb = 0; nb < 8; nb++) {
                s[nb][0] = exp2f((s[nb][0] - mn0) * FC); rs0 += s[nb][0];
                s[nb][1] = exp2f((s[nb][1] - mn0) * FC); rs0 += s[nb][1];
                s[nb][2] = exp2f((s[nb][2] - mn1) * FC); rs1 += s[nb][2];
                s[nb][3] = exp2f((s[nb][3] - mn1) * FC); rs1 += s[nb][3];
            }
            rs0 += __shfl_xor_sync(0xffffffffu, rs0, 1);
            rs0 += __shfl_xor_sync(0xffffffffu, rs0, 2);
            rs1 += __shfl_xor_sync(0xffffffffu, rs1, 1);
            rs1 += __shfl_xor_sync(0xffffffffu, rs1, 2);
            l0 += rs0; l1 += rs1;

            // ---- PV: o += P . V (Ph*Vh + Pl*Vh) ----
#pragma unroll
            for (int j = 0; j < 4; j++) {
                uint32_t pha[4], pla[4];
#pragma unroll
                for (int hq = 0; hq < 4; hq++) {
                    const int nb = 2 * j + (hq >> 1);
                    const int e  = (hq & 1) << 1;
                    const float p0 = s[nb][e], p1 = s[nb][e + 1];
                    __half2 h = __floats2half2_rn(p0, p1);
                    float2 hf = __half22float2(h);
                    __half2 l = __floats2half2_rn(p0 - hf.x, p1 - hf.y);
                    pha[hq] = *reinterpret_cast<uint32_t*>(&h);
                    pla[hq] = *reinterpret_cast<uint32_t*>(&l);
                }
#pragma unroll
                for (int g16 = 0; g16 < 8; g16++) {
                    uint32_t bh[4];
                    const uint32_t ba = (uint32_t)(g16 * 16 + brow) * 144 + bko + j * 32;
                    LDSM4(bh[0], bh[1], bh[2], bh[3], vb_h + ba);
                    MMA16816(o[2 * g16],     pha, bh);
                    MMA16816(o[2 * g16],     pla, bh);
                    MMA16816(o[2 * g16 + 1], pha, bh + 2);
                    MMA16816(o[2 * g16 + 1], pla, bh + 2);
                }
            }
        }
        __syncthreads();
        buf ^= 1;
    }

    // ---- epilogue: normalize, f16 hi only ----
    const float inv0 = 1.f / l0, inv1 = 1.f / l1;
    const int r0 = wrow + (lane >> 2);
    const long base0 = ((long)z * SEQ + r0) * HD + ((lane & 3) << 1);
    const long base1 = base0 + 8 * HD;
#pragma unroll
    for (int nb = 0; nb < 16; nb++) {
        *(__half2*)(oah + base0 + nb * 8) =
            __floats2half2_rn(o[nb][0] * inv0, o[nb][1] * inv0);
        *(__half2*)(oah + base1 + nb * 8) =
            __floats2half2_rn(o[nb][2] * inv1, o[nb][3] * inv1);
    }
}

// ---------------- RoPE: fp32 in, f16 hi(/lo) out ----------------
template<bool WLO>
__global__ __launch_bounds__(256)
void rope_k(const float* __restrict__ buf, __half* __restrict__ dh,
            __half* __restrict__ dl, const int* __restrict__ pos, int heads)
{
    int idx = blockIdx.x * 256 + threadIdx.x;
    int total = heads * SEQ * 64;
    if (idx >= total) return;
    int i = idx & 63;
    int l = (idx >> 6) % SEQ;
    int n = idx / (SEQ * 64);

    float invf = exp2f(-(float)i * 0.31143075889569023f);
    float ang  = (float)pos[l] * invf;
    float q  = rintf(ang * 0.15915494309189535f);
    float r  = ang - q * 6.28125f;
    r        = r   - q * 1.9353071795864769e-3f;
    float s, c;
    sincosf(r, &s, &c);

    const long base = ((long)n * SEQ + l) * HD;
    const float x1 = buf[base + i], x2 = buf[base + i + 64];
    const float y1 = x1 * c - x2 * s;
    const float y2 = x2 * c + x1 * s;
    const __half h1 = __float2half_rn(y1);
    const __half h2 = __float2half_rn(y2);
    dh[base + i]      = h1;
    dh[base + i + 64] = h2;
    if (WLO) {
        dl[base + i]      = __float2half_rn(y1 - __half2float(h1));
        dl[base + i + 64] = __float2half_rn(y2 - __half2float(h2));
    }
}

// ---------------- V transpose: fp32 [kv][S][128] -> f16 [kv][128][S] ----------------
__global__ __launch_bounds__(256)
void transpose_vh(const float* __restrict__ v, __half* __restrict__ vt)
{
    __shared__ float t[32][33];
    int h  = blockIdx.z;
    int s0 = blockIdx.x * 32, d0 = blockIdx.y * 32;
    const float* src = v + ((long)h * SEQ + s0) * HD + d0;
#pragma unroll
    for (int yy = threadIdx.y; yy < 32; yy += 8)
        t[yy][threadIdx.x] = src[yy * HD + threadIdx.x];
    __syncthreads();
    __half* dst = vt + ((long)h * HD + d0) * SEQ + s0;
#pragma unroll
    for (int yy = threadIdx.y; yy < 32; yy += 8)
        dst[(long)yy * SEQ + threadIdx.x] = __float2half_rn(t[threadIdx.x][yy]);
}

// ---------------- fp32 -> f16 weight rounding ----------------
__global__ __launch_bounds__(256)
void cvt16_k(const float* __restrict__ s, __half* __restrict__ d, int n)
{
    int i = (blockIdx.x * 256 + threadIdx.x) << 2;
    if (i >= n) return;
    float4 v = *(const float4*)(s + i);
    ((__half2*)(d + i))[0] = __floats2half2_rn(v.x, v.y);
    ((__half2*)(d + i))[1] = __floats2half2_rn(v.z, v.w);
}

// ---------------- launch ----------------
extern "C" void kernel_launch(void* const* d_in, const int* in_sizes, int n_in,
                              void* d_out, int out_size)
{
    const float* qhid = (const float*)d_in[0];
    const float* khid = (const float*)d_in[1];
    const float* vhid = (const float*)d_in[2];
    const int*   pos  = (const int*)  d_in[4];
    const float* qw   = (const float*)d_in[5];
    const float* kw   = (const float*)d_in[6];
    const float* vw   = (const float*)d_in[7];
    const float* ow   = (const float*)d_in[8];
    float*       out  = (float*)d_out;

    float *qb, *kb, *vb;
    __half *qhh, *qll, *khh, *vth, *ahh, *wh;
    cudaGetSymbolAddress((void**)&qb,  g_q);
    cudaGetSymbolAddress((void**)&kb,  g_k);
    cudaGetSymbolAddress((void**)&vb,  g_v);
    cudaGetSymbolAddress((void**)&qhh, g_qh);
    cudaGetSymbolAddress((void**)&qll, g_ql);
    cudaGetSymbolAddress((void**)&khh, g_kh);
    cudaGetSymbolAddress((void**)&vth, g_vth);
    cudaGetSymbolAddress((void**)&ahh, g_ah);
    cudaGetSymbolAddress((void**)&wh,  g_wh);

    cudaFuncSetAttribute(tgemm<true,  true >, cudaFuncAttributeMaxDynamicSharedMemorySize, GSMB);
    cudaFuncSetAttribute(tgemm<false, false>, cudaFuncAttributeMaxDynamicSharedMemorySize, GSMB);
    cudaFuncSetAttribute(flash_k,             cudaFuncAttributeMaxDynamicSharedMemorySize, FSMEM);

    const long HH  = (long)SEQ * HIDDEN;
    const long HDW = (long)HD * HIDDEN;
    const long SH  = (long)SEQ * HD;

    // weights -> f16
    cvt16_k<<<(HIDDEN * HIDDEN) / 1024, 256>>>(qw, wh + QW_OFF, HIDDEN * HIDDEN);
    cvt16_k<<<(256 * HIDDEN)    / 1024, 256>>>(kw, wh + KW_OFF, 256 * HIDDEN);
    cvt16_k<<<(256 * HIDDEN)    / 1024, 256>>>(vw, wh + VW_OFF, 256 * HIDDEN);
    cvt16_k<<<(HIDDEN * HIDDEN) / 1024, 256>>>(ow, wh + OW_OFF, HIDDEN * HIDDEN);

    // Q projection (NT): A fp32, 2-term
    tgemm<true, true><<<dim3(1, 16, NH), 256, GSMB>>>(qhid, nullptr, wh + QW_OFF, qb,
        nullptr, nullptr, nullptr, 99,
        HIDDEN, HIDDEN, HIDDEN, HD, HH, HDW, SH);
    // K+V projections merged in one launch (z<2: K, z>=2: V)
    tgemm<true, true><<<dim3(1, 16, 2 * NKV), 256, GSMB>>>(khid, nullptr, wh + KW_OFF, kb,
        vhid, wh + VW_OFF, vb, NKV,
        HIDDEN, HIDDEN, HIDDEN, HD, HH, HDW, SH);

    // RoPE -> f16 (q: hi+lo, k: hi only)
    rope_k<true ><<<(NH  * SEQ * 64 + 255) / 256, 256>>>(qb, qhh, qll, pos, NH);
    rope_k<false><<<(NKV * SEQ * 64 + 255) / 256, 256>>>(kb, khh, nullptr, pos, NKV);

    // V transpose -> f16 hi
    transpose_vh<<<dim3(64, 4, NKV), dim3(32, 8)>>>(vb, vth);

    // fused attention -> attn f16 hi
    flash_k<<<dim3(NH, 32), 128, FSMEM>>>(qhh, qll, khh, vth, ahh);

    // O projection: A = attn f16 (1-term), B = ow f16 (per-head offset z*128)
    tgemm<false, false><<<dim3(16, 16, NH), 256, GSMB>>>(nullptr, ahh, wh + OW_OFF, out,
        nullptr, nullptr, nullptr, 99,
        HD, HD, HIDDEN, HIDDEN, SH, (long)HD, HH);
}

// round 7
// speedup vs baseline: 6.3483x; 1.1739x over previous
#include <cuda_runtime.h>
#include <cuda_fp16.h>
#include <math.h>
#include <stdint.h>

#define SEQ     2048
#define HIDDEN  2048
#define HD      128
#define NH      16
#define NKV     2

// ---------------- scratch (device globals) ----------------
__device__ __align__(16) float  g_q [(size_t)NH  * SEQ * HD];
__device__ __align__(16) float  g_k [(size_t)NKV * SEQ * HD];
__device__ __align__(16) float  g_v [(size_t)NKV * SEQ * HD];
__device__ __align__(16) __half g_qh [(size_t)NH  * SEQ * HD];
__device__ __align__(16) __half g_kh [(size_t)NKV * SEQ * HD];
__device__ __align__(16) __half g_vth[(size_t)NKV * HD * SEQ];
__device__ __align__(16) __half g_ah [(size_t)NH  * SEQ * HD];
// packed f16 weights: qw | kw | vw | ow (element offsets)
#define QW_OFF 0
#define KW_OFF 4194304
#define VW_OFF 4718592
#define OW_OFF 5242880
#define W_TOT  9437184
__device__ __align__(16) __half g_wh[W_TOT];

// ================= helpers =================
__device__ __forceinline__ uint32_t smem_u32(const void* p) {
    uint32_t a;
    asm("{ .reg .u64 t; cvta.to.shared.u64 t, %1; cvt.u32.u64 %0, t; }" : "=r"(a) : "l"(p));
    return a;
}

#define LDSM4(r0, r1, r2, r3, addr) \
    asm volatile("ldmatrix.sync.aligned.m8n8.x4.shared.b16 {%0,%1,%2,%3}, [%4];" \
                 : "=r"(r0), "=r"(r1), "=r"(r2), "=r"(r3) : "r"(addr))

#define MMA16816(c, a, b) \
    asm volatile("mma.sync.aligned.m16n8k16.row.col.f32.f16.f16.f32 " \
                 "{%0,%1,%2,%3}, {%4,%5,%6,%7}, {%8,%9}, {%0,%1,%2,%3};" \
                 : "+f"((c)[0]), "+f"((c)[1]), "+f"((c)[2]), "+f"((c)[3]) \
                 : "r"((a)[0]), "r"((a)[1]), "r"((a)[2]), "r"((a)[3]), \
                   "r"((b)[0]), "r"((b)[1]))

#define CPA16(dst, src) \
    asm volatile("cp.async.cg.shared.global [%0], [%1], 16;" :: "r"(dst), "l"(src))
#define CPA_COMMIT()  asm volatile("cp.async.commit_group;")
#define CPA_WAIT0()   asm volatile("cp.async.wait_group 0;")
#define CPA_WAIT1()   asm volatile("cp.async.wait_group 1;")

// ================= projection GEMM (pure f16, 1-term) =================
// per-buffer smem: AH [0,10240), BH [10240,20480)
#define ROWB  80
#define TILEB (128 * ROWB)
#define BUF1  (2 * TILEB)
#define GSMB  (2 * BUF1)

__device__ __forceinline__ void cvt_hi16(const float* __restrict__ xs,
                                         uint32_t* __restrict__ hw)
{
#pragma unroll
    for (int q = 0; q < 8; q++) {
        __half2 h = __floats2half2_rn(xs[2 * q], xs[2 * q + 1]);
        hw[q] = *reinterpret_cast<uint32_t*>(&h);
    }
}

// AF32: A fp32 in gmem (cvt to f16 in loader). else A f16 via cp.async.
// Dual pointer sets + zsplit for merged launches.
template<bool AF32>
__global__ __launch_bounds__(256, 2)
void tgemm(const float* __restrict__ Af, const __half* __restrict__ Ahg,
           const __half* __restrict__ Bhg, float* __restrict__ Cb,
           const float* __restrict__ Af2, const __half* __restrict__ Bhg2,
           float* __restrict__ Cb2, int zsplit,
           int K, int lda, int ldb, int ldc, long sA, long sB, long sC)
{
    extern __shared__ char dsm[];
    const int tid  = threadIdx.x;
    const int wid  = tid >> 5;
    const int lane = tid & 31;
    const int wm   = (wid >> 2) << 6;
    const int wn   = (wid & 3) << 5;
    int z          = blockIdx.z;
    const int m0   = blockIdx.y << 7;
    const int n0   = blockIdx.x << 7;

    const float*  Afz = Af;
    const __half* Bz  = Bhg;
    float*        Cz  = Cb;
    if (z >= zsplit) { Afz = Af2; Bz = Bhg2; Cz = Cb2; z -= zsplit; }

    const float*  A  = AF32 ? (Afz + (long)z * sA + (long)m0 * lda) : nullptr;
    const __half* Ah = AF32 ? nullptr : (Ahg + (long)z * sA + (long)m0 * lda);
    const __half* B  = Bz + (long)z * sB + (long)n0 * ldb;
    float*        C  = Cz + (long)z * sC;

    const int nch  = K >> 5;
    const int lrow = tid >> 1, lhalf = tid & 1;
    const int soff = lrow * ROWB + lhalf * 32;

    float acc[4][4][4];
#pragma unroll
    for (int i = 0; i < 4; i++)
#pragma unroll
        for (int j = 0; j < 4; j++)
#pragma unroll
            for (int q = 0; q < 4; q++) acc[i][j][q] = 0.f;

    const uint32_t smbase = smem_u32(dsm);
    const int a_row  = wm + (lane & 15);
    const int a_koff = (lane >> 4) << 4;
    const int b_row  = wn + (lane & 7) + ((lane >> 4) & 1) * 8;
    const int b_koff = ((lane >> 3) & 1) << 4;

    const uint32_t cp_off  = (uint32_t)lrow * ROWB + (uint32_t)lhalf * 32;
    const long     cp_srcb = (long)lrow * ldb + lhalf * 16;
    const long     cp_srca = (long)lrow * lda + lhalf * 16;

    float ra[16];
    // ---- prologue: chunk 0 ----
    {
        CPA16(smbase + TILEB + cp_off,      B + cp_srcb);
        CPA16(smbase + TILEB + cp_off + 16, B + cp_srcb + 8);
        if (AF32) {
            const float4* pa = (const float4*)(A + (long)lrow * lda + lhalf * 16);
#pragma unroll
            for (int q = 0; q < 4; q++) *(float4*)(ra + 4 * q) = pa[q];
            uint32_t hw[8];
            cvt_hi16(ra, hw);
            *(uint4*)(dsm + soff)      = make_uint4(hw[0], hw[1], hw[2], hw[3]);
            *(uint4*)(dsm + soff + 16) = make_uint4(hw[4], hw[5], hw[6], hw[7]);
        } else {
            CPA16(smbase + cp_off,      Ah + cp_srca);
            CPA16(smbase + cp_off + 16, Ah + cp_srca + 8);
        }
        CPA_COMMIT();
        CPA_WAIT0();
    }
    __syncthreads();

    for (int i = 0; i < nch; i++) {
        // issue next chunk's loads before MMA
        if (i + 1 < nch) {
            const int k0 = (i + 1) << 5;
            const uint32_t bb = smbase + ((i + 1) & 1) * BUF1;
            CPA16(bb + TILEB + cp_off,      B + k0 + cp_srcb);
            CPA16(bb + TILEB + cp_off + 16, B + k0 + cp_srcb + 8);
            if (AF32) {
                const float4* pa = (const float4*)(A + (long)lrow * lda + k0 + lhalf * 16);
#pragma unroll
                for (int q = 0; q < 4; q++) *(float4*)(ra + 4 * q) = pa[q];
            } else {
                CPA16(bb + cp_off,      Ah + k0 + cp_srca);
                CPA16(bb + cp_off + 16, Ah + k0 + cp_srca + 8);
            }
            CPA_COMMIT();
        }
        // MMA on current buffer
        const uint32_t tb = smbase + (i & 1) * BUF1;
#pragma unroll
        for (int ks = 0; ks < 2; ks++) {
            uint32_t bh[4][2];
            const uint32_t ka = ks * 32 + a_koff;
            const uint32_t kb = ks * 32 + b_koff;
#pragma unroll
            for (int p = 0; p < 2; p++) {
                uint32_t r0, r1, r2, r3;
                LDSM4(r0, r1, r2, r3, tb + TILEB + (uint32_t)(b_row + p * 16) * ROWB + kb);
                bh[2 * p][0] = r0; bh[2 * p][1] = r1;
                bh[2 * p + 1][0] = r2; bh[2 * p + 1][1] = r3;
            }
#pragma unroll
            for (int mi = 0; mi < 4; mi++) {
                uint32_t ah[4];
                LDSM4(ah[0], ah[1], ah[2], ah[3],
                      tb + (uint32_t)(a_row + mi * 16) * ROWB + ka);
#pragma unroll
                for (int ni = 0; ni < 4; ni++) MMA16816(acc[mi][ni], ah, bh[ni]);
            }
        }
        // store next A chunk (fp32 path)
        if (i + 1 < nch) {
            if (AF32) {
                char* buf = dsm + ((i + 1) & 1) * BUF1;
                uint32_t hw[8];
                cvt_hi16(ra, hw);
                *(uint4*)(buf + soff)      = make_uint4(hw[0], hw[1], hw[2], hw[3]);
                *(uint4*)(buf + soff + 16) = make_uint4(hw[4], hw[5], hw[6], hw[7]);
            }
            CPA_WAIT0();
        }
        __syncthreads();
    }

    // epilogue
    const int g = lane >> 2, t = lane & 3;
#pragma unroll
    for (int mi = 0; mi < 4; mi++) {
        const int r0 = m0 + wm + mi * 16 + g;
#pragma unroll
        for (int ni = 0; ni < 4; ni++) {
            const int cc = n0 + wn + ni * 8 + t * 2;
            *(float2*)(C + (long)r0 * ldc + cc)       = make_float2(acc[mi][ni][0], acc[mi][ni][1]);
            *(float2*)(C + (long)(r0 + 8) * ldc + cc) = make_float2(acc[mi][ni][2], acc[mi][ni][3]);
        }
    }
}

// ================= flash attention: pure f16, 64 Q rows / CTA, 128 threads =================
// smem: QH [0,17408), K bufs [17408,+17408x2), VT bufs [52224,+18432x2)  total 89088
#define K_OFF  17408
#define KBUFB  17408
#define V_OFF  52224
#define VBUFB  18432
#define FSMEM  89088
#define FC     0.12751744f   // log2(e) / sqrt(128)

__device__ __forceinline__ void kv_prefetch(uint32_t smb, int buf, int kv0,
    const __half* __restrict__ khp, const __half* __restrict__ vhp, int tid)
{
#pragma unroll
    for (int i = 0; i < 8; i++) {
        int t = tid + (i << 7);
        int unit = t & 15, row = t >> 4;            // 0..63
        CPA16(smb + K_OFF + buf * KBUFB + row * 272 + unit * 16,
              khp + (long)(kv0 + row) * HD + unit * 8);
    }
#pragma unroll
    for (int i = 0; i < 8; i++) {
        int t = tid + (i << 7);
        int unit = t & 7, row = t >> 3;             // 0..127
        CPA16(smb + V_OFF + buf * VBUFB + row * 144 + unit * 16,
              vhp + (long)row * SEQ + kv0 + unit * 8);
    }
}

__global__ __launch_bounds__(128)
void flash_k(const __half* __restrict__ qhg, const __half* __restrict__ khg,
             const __half* __restrict__ vhg, __half* __restrict__ oah)
{
    extern __shared__ char dsm[];
    const uint32_t smb = smem_u32(dsm);
    const int tid  = threadIdx.x;
    const int w    = tid >> 5;
    const int lane = tid & 31;
    const int z    = blockIdx.x;
    const int mb   = 31 - blockIdx.y;     // heavy blocks first
    const int kvh  = z >> 3;
    const int m0   = mb << 6;
    const int nt   = mb + 1;

    const __half* qhp = qhg + ((long)z * SEQ + m0) * HD;
    const __half* khp = khg + (long)kvh * SEQ * HD;
    const __half* vhp = vhg + (long)kvh * HD * SEQ;

    // Q -> smem (one-time): 64 rows x 8 16B-units
#pragma unroll
    for (int i = 0; i < 8; i++) {
        int t = tid + (i << 7);
        int unit = t & 15, row = t >> 4;
        CPA16(smb + row * 272 + unit * 16, qhp + (long)row * HD + unit * 8);
    }
    CPA_COMMIT();
    kv_prefetch(smb, 0, 0, khp, vhp, tid);
    CPA_COMMIT();

    float o[16][4];
#pragma unroll
    for (int nb = 0; nb < 16; nb++)
#pragma unroll
        for (int q = 0; q < 4; q++) o[nb][q] = 0.f;
    float mr0 = -1e30f, mr1 = -1e30f, l0 = 0.f, l1 = 0.f;

    const int wrow = m0 + (w << 4);
    const uint32_t qa_h = smb + (uint32_t)((w << 4) + (lane & 15)) * 272 + ((lane >> 4) << 4);
    const uint32_t brow = (lane & 7) + ((lane >> 4) & 1) * 8;
    const uint32_t bko  = ((lane >> 3) & 1) << 4;

    int buf = 0;
    for (int it = 0; it < nt; it++) {
        if (it + 1 < nt) {
            kv_prefetch(smb, buf ^ 1, (it + 1) << 6, khp, vhp, tid);
            CPA_COMMIT();
            CPA_WAIT1();
        } else {
            CPA_WAIT0();
        }
        __syncthreads();

        const int kv0 = it << 6;
        {
            const uint32_t kb_h = smb + K_OFF + buf * KBUFB;
            const uint32_t vb_h = smb + V_OFF + buf * VBUFB;

            float s[8][4];
#pragma unroll
            for (int nb = 0; nb < 8; nb++)
#pragma unroll
                for (int q = 0; q < 4; q++) s[nb][q] = 0.f;

            // ---- scores: s = Q . K^T ----
#pragma unroll
            for (int j = 0; j < 8; j++) {
                uint32_t ah[4];
                LDSM4(ah[0], ah[1], ah[2], ah[3], qa_h + j * 32);
#pragma unroll
                for (int g16 = 0; g16 < 4; g16++) {
                    uint32_t bh[4];
                    const uint32_t ba = (uint32_t)(g16 * 16 + brow) * 272 + bko + j * 32;
                    LDSM4(bh[0], bh[1], bh[2], bh[3], kb_h + ba);
                    MMA16816(s[2 * g16],     ah, bh);
                    MMA16816(s[2 * g16 + 1], ah, bh + 2);
                }
            }

            // ---- causal mask ----
            const int r0 = wrow + (lane >> 2);
            const int c0 = kv0 + ((lane & 3) << 1);
            if (kv0 + 63 > wrow) {
#pragma unroll
                for (int nb = 0; nb < 8; nb++) {
                    const int c = c0 + nb * 8;
                    if (c     > r0    ) s[nb][0] = -1e30f;
                    if (c + 1 > r0    ) s[nb][1] = -1e30f;
                    if (c     > r0 + 8) s[nb][2] = -1e30f;
                    if (c + 1 > r0 + 8) s[nb][3] = -1e30f;
                }
            }

            // ---- online softmax ----
            float tm0 = -1e30f, tm1 = -1e30f;
#pragma unroll
            for (int nb = 0; nb < 8; nb++) {
                tm0 = fmaxf(tm0, fmaxf(s[nb][0], s[nb][1]));
                tm1 = fmaxf(tm1, fmaxf(s[nb][2], s[nb][3]));
            }
            tm0 = fmaxf(tm0, __shfl_xor_sync(0xffffffffu, tm0, 1));
            tm0 = fmaxf(tm0, __shfl_xor_sync(0xffffffffu, tm0, 2));
            tm1 = fmaxf(tm1, __shfl_xor_sync(0xffffffffu, tm1, 1));
            tm1 = fmaxf(tm1, __shfl_xor_sync(0xffffffffu, tm1, 2));
            const float mn0 = fmaxf(mr0, tm0), mn1 = fmaxf(mr1, tm1);
            const float sf0 = exp2f((mr0 - mn0) * FC);
            const float sf1 = exp2f((mr1 - mn1) * FC);
            mr0 = mn0; mr1 = mn1;
            l0 *= sf0;  l1 *= sf1;
#pragma unroll
            for (int nb = 0; nb < 16; nb++) {
                o[nb][0] *= sf0; o[nb][1] *= sf0;
                o[nb][2] *= sf1; o[nb][3] *= sf1;
            }
            float rs0 = 0.f, rs1 = 0.f;
#pragma unroll
            for (int nb = 0; nb < 8; nb++) {
                s[nb][0] = exp2f((s[nb][0] - mn0) * FC); rs0 += s[nb][0];
                s[nb][1] = exp2f((s[nb][1] - mn0) * FC); rs0 += s[nb][1];
                s[nb][2] = exp2f((s[nb][2] - mn1) * FC); rs1 += s[nb][2];
                s[nb][3] = exp2f((s[nb][3] - mn1) * FC); rs1 += s[nb][3];
            }
            rs0 += __shfl_xor_sync(0xffffffffu, rs0, 1);
            rs0 += __shfl_xor_sync(0xffffffffu, rs0, 2);
            rs1 += __shfl_xor_sync(0xffffffffu, rs1, 1);
            rs1 += __shfl_xor_sync(0xffffffffu, rs1, 2);
            l0 += rs0; l1 += rs1;

            // ---- PV: o += P . V ----
#pragma unroll
            for (int j = 0; j < 4; j++) {
                uint32_t pha[4];
#pragma unroll
                for (int hq = 0; hq < 4; hq++) {
                    const int nb = 2 * j + (hq >> 1);
                    const int e  = (hq & 1) << 1;
                    __half2 h = __floats2half2_rn(s[nb][e], s[nb][e + 1]);
                    pha[hq] = *reinterpret_cast<uint32_t*>(&h);
                }
#pragma unroll
                for (int g16 = 0; g16 < 8; g16++) {
                    uint32_t bh[4];
                    const uint32_t ba = (uint32_t)(g16 * 16 + brow) * 144 + bko + j * 32;
                    LDSM4(bh[0], bh[1], bh[2], bh[3], vb_h + ba);
                    MMA16816(o[2 * g16],     pha, bh);
                    MMA16816(o[2 * g16 + 1], pha, bh + 2);
                }
            }
        }
        __syncthreads();
        buf ^= 1;
    }

    // ---- epilogue: normalize, f16 ----
    const float inv0 = 1.f / l0, inv1 = 1.f / l1;
    const int r0 = wrow + (lane >> 2);
    const long base0 = ((long)z * SEQ + r0) * HD + ((lane & 3) << 1);
    const long base1 = base0 + 8 * HD;
#pragma unroll
    for (int nb = 0; nb < 16; nb++) {
        *(__half2*)(oah + base0 + nb * 8) =
            __floats2half2_rn(o[nb][0] * inv0, o[nb][1] * inv0);
        *(__half2*)(oah + base1 + nb * 8) =
            __floats2half2_rn(o[nb][2] * inv1, o[nb][3] * inv1);
    }
}

// ---------------- RoPE (merged q+k): fp32 in, f16 out ----------------
__global__ __launch_bounds__(256)
void rope_all(const float* __restrict__ qb, const float* __restrict__ kb,
              __half* __restrict__ qh, __half* __restrict__ kh,
              const int* __restrict__ pos)
{
    int idx = blockIdx.x * 256 + threadIdx.x;
    const int total = (NH + NKV) * SEQ * 64;
    if (idx >= total) return;
    int i = idx & 63;
    int l = (idx >> 6) % SEQ;
    int n = idx / (SEQ * 64);

    float invf = exp2f(-(float)i * 0.31143075889569023f);
    float ang  = (float)pos[l] * invf;
    float q  = rintf(ang * 0.15915494309189535f);
    float r  = ang - q * 6.28125f;
    r        = r   - q * 1.9353071795864769e-3f;
    float s, c;
    sincosf(r, &s, &c);

    const float* src;
    __half* dst;
    if (n < NH) { src = qb + ((long)n * SEQ + l) * HD;        dst = qh + ((long)n * SEQ + l) * HD; }
    else        { src = kb + ((long)(n - NH) * SEQ + l) * HD; dst = kh + ((long)(n - NH) * SEQ + l) * HD; }

    const float x1 = src[i], x2 = src[i + 64];
    dst[i]      = __float2half_rn(x1 * c - x2 * s);
    dst[i + 64] = __float2half_rn(x2 * c + x1 * s);
}

// ---------------- V transpose: fp32 [kv][S][128] -> f16 [kv][128][S] ----------------
__global__ __launch_bounds__(256)
void transpose_vh(const float* __restrict__ v, __half* __restrict__ vt)
{
    __shared__ float t[32][33];
    int h  = blockIdx.z;
    int s0 = blockIdx.x * 32, d0 = blockIdx.y * 32;
    const float* src = v + ((long)h * SEQ + s0) * HD + d0;
#pragma unroll
    for (int yy = threadIdx.y; yy < 32; yy += 8)
        t[yy][threadIdx.x] = src[yy * HD + threadIdx.x];
    __syncthreads();
    __half* dst = vt + ((long)h * HD + d0) * SEQ + s0;
#pragma unroll
    for (int yy = threadIdx.y; yy < 32; yy += 8)
        dst[(long)yy * SEQ + threadIdx.x] = __float2half_rn(t[threadIdx.x][yy]);
}

// ---------------- fp32 -> f16 all weights in one launch ----------------
__global__ __launch_bounds__(256)
void cvt16_all(const float* __restrict__ qw, const float* __restrict__ kw,
               const float* __restrict__ vw, const float* __restrict__ ow,
               __half* __restrict__ d)
{
    int e = (blockIdx.x * 256 + threadIdx.x) << 2;
    if (e >= W_TOT) return;
    const float* s;
    if      (e < KW_OFF) s = qw + e;
    else if (e < VW_OFF) s = kw + (e - KW_OFF);
    else if (e < OW_OFF) s = vw + (e - VW_OFF);
    else                 s = ow + (e - OW_OFF);
    float4 v = *(const float4*)s;
    ((__half2*)(d + e))[0] = __floats2half2_rn(v.x, v.y);
    ((__half2*)(d + e))[1] = __floats2half2_rn(v.z, v.w);
}

// ---------------- launch ----------------
extern "C" void kernel_launch(void* const* d_in, const int* in_sizes, int n_in,
                              void* d_out, int out_size)
{
    const float* qhid = (const float*)d_in[0];
    const float* khid = (const float*)d_in[1];
    const float* vhid = (const float*)d_in[2];
    const int*   pos  = (const int*)  d_in[4];
    const float* qw   = (const float*)d_in[5];
    const float* kw   = (const float*)d_in[6];
    const float* vw   = (const float*)d_in[7];
    const float* ow   = (const float*)d_in[8];
    float*       out  = (float*)d_out;

    float *qb, *kb, *vb;
    __half *qhh, *khh, *vth, *ahh, *wh;
    cudaGetSymbolAddress((void**)&qb,  g_q);
    cudaGetSymbolAddress((void**)&kb,  g_k);
    cudaGetSymbolAddress((void**)&vb,  g_v);
    cudaGetSymbolAddress((void**)&qhh, g_qh);
    cudaGetSymbolAddress((void**)&khh, g_kh);
    cudaGetSymbolAddress((void**)&vth, g_vth);
    cudaGetSymbolAddress((void**)&ahh, g_ah);
    cudaGetSymbolAddress((void**)&wh,  g_wh);

    cudaFuncSetAttribute(tgemm<true >, cudaFuncAttributeMaxDynamicSharedMemorySize, GSMB);
    cudaFuncSetAttribute(tgemm<false>, cudaFuncAttributeMaxDynamicSharedMemorySize, GSMB);
    cudaFuncSetAttribute(flash_k,      cudaFuncAttributeMaxDynamicSharedMemorySize, FSMEM);

    const long HH  = (long)SEQ * HIDDEN;
    const long HDW = (long)HD * HIDDEN;
    const long SH  = (long)SEQ * HD;

    // all weights -> f16 (single launch)
    cvt16_all<<<(W_TOT / 4 + 255) / 256, 256>>>(qw, kw, vw, ow, wh);

    // Q projection (NT)
    tgemm<true><<<dim3(1, 16, NH), 256, GSMB>>>(qhid, nullptr, wh + QW_OFF, qb,
        nullptr, nullptr, nullptr, 99,
        HIDDEN, HIDDEN, HIDDEN, HD, HH, HDW, SH);
    // K+V projections merged (z<2: K, z>=2: V)
    tgemm<true><<<dim3(1, 16, 2 * NKV), 256, GSMB>>>(khid, nullptr, wh + KW_OFF, kb,
        vhid, wh + VW_OFF, vb, NKV,
        HIDDEN, HIDDEN, HIDDEN, HD, HH, HDW, SH);

    // RoPE q+k merged -> f16
    rope_all<<<((NH + NKV) * SEQ * 64 + 255) / 256, 256>>>(qb, kb, qhh, khh, pos);

    // V transpose -> f16
    transpose_vh<<<dim3(64, 4, NKV), dim3(32, 8)>>>(vb, vth);

    // fused attention -> attn f16
    flash_k<<<dim3(NH, 32), 128, FSMEM>>>(qhh, khh, vth, ahh);

    // O projection: A = attn f16, B = ow f16 (per-head offset z*128)
    tgemm<false><<<dim3(16, 16, NH), 256, GSMB>>>(nullptr, ahh, wh + OW_OFF, out,
        nullptr, nullptr, nullptr, 99,
        HD, HD, HIDDEN, HIDDEN, SH, (long)HD, HH);
}

// round 8
// speedup vs baseline: 6.6259x; 1.0437x over previous
#include <cuda_runtime.h>
#include <cuda_fp16.h>
#include <math.h>
#include <stdint.h>

#define SEQ     2048
#define HIDDEN  2048
#define HD      128
#define NH      16
#define NKV     2

// ---------------- scratch (device globals) ----------------
__device__ __align__(16) float  g_q [(size_t)NH  * SEQ * HD];
__device__ __align__(16) float  g_k [(size_t)NKV * SEQ * HD];
__device__ __align__(16) float  g_v [(size_t)NKV * SEQ * HD];
__device__ __align__(16) __half g_qh [(size_t)NH  * SEQ * HD];
__device__ __align__(16) __half g_kh [(size_t)NKV * SEQ * HD];
__device__ __align__(16) __half g_vth[(size_t)NKV * HD * SEQ];
__device__ __align__(16) __half g_ah [(size_t)NH  * SEQ * HD];
// packed f16 weights: qw | kw | vw | ow (element offsets)
#define QW_OFF 0
#define KW_OFF 4194304
#define VW_OFF 4718592
#define OW_OFF 5242880
#define W_TOT  9437184
__device__ __align__(16) __half g_wh[W_TOT];

// ================= helpers =================
__device__ __forceinline__ uint32_t smem_u32(const void* p) {
    uint32_t a;
    asm("{ .reg .u64 t; cvta.to.shared.u64 t, %1; cvt.u32.u64 %0, t; }" : "=r"(a) : "l"(p));
    return a;
}

#define LDSM4(r0, r1, r2, r3, addr) \
    asm volatile("ldmatrix.sync.aligned.m8n8.x4.shared.b16 {%0,%1,%2,%3}, [%4];" \
                 : "=r"(r0), "=r"(r1), "=r"(r2), "=r"(r3) : "r"(addr))

#define MMA16816(c, a, b) \
    asm volatile("mma.sync.aligned.m16n8k16.row.col.f32.f16.f16.f32 " \
                 "{%0,%1,%2,%3}, {%4,%5,%6,%7}, {%8,%9}, {%0,%1,%2,%3};" \
                 : "+f"((c)[0]), "+f"((c)[1]), "+f"((c)[2]), "+f"((c)[3]) \
                 : "r"((a)[0]), "r"((a)[1]), "r"((a)[2]), "r"((a)[3]), \
                   "r"((b)[0]), "r"((b)[1]))

#define CPA16(dst, src) \
    asm volatile("cp.async.cg.shared.global [%0], [%1], 16;" :: "r"(dst), "l"(src))
#define CPA_COMMIT()  asm volatile("cp.async.commit_group;")
#define CPA_WAIT0()   asm volatile("cp.async.wait_group 0;")
#define CPA_WAIT1()   asm volatile("cp.async.wait_group 1;")

// ================= projection GEMM (pure f16, 1-term) =================
// per-buffer smem: AH [0,10240), BH [10240,20480)
#define ROWB  80
#define TILEB (128 * ROWB)
#define BUF1  (2 * TILEB)
#define GSMB  (2 * BUF1)

__device__ __forceinline__ void cvt_hi16(const float* __restrict__ xs,
                                         uint32_t* __restrict__ hw)
{
#pragma unroll
    for (int q = 0; q < 8; q++) {
        __half2 h = __floats2half2_rn(xs[2 * q], xs[2 * q + 1]);
        hw[q] = *reinterpret_cast<uint32_t*>(&h);
    }
}

// AF32: A fp32 in gmem (cvt to f16 in loader). else A f16 via cp.async.
// Three problem pointer sets selected by z (merged Q/K/V launch).
template<bool AF32>
__global__ __launch_bounds__(256, 2)
void tgemm(const float* __restrict__ Af0, const __half* __restrict__ Ahg,
           const __half* __restrict__ B0, float* __restrict__ C0,
           const float* __restrict__ Af1, const __half* __restrict__ B1,
           float* __restrict__ C1,
           const float* __restrict__ Af2, const __half* __restrict__ B2,
           float* __restrict__ C2, int z1, int z2,
           int K, int lda, int ldb, int ldc, long sA, long sB, long sC)
{
    extern __shared__ char dsm[];
    const int tid  = threadIdx.x;
    const int wid  = tid >> 5;
    const int lane = tid & 31;
    const int wm   = (wid >> 2) << 6;
    const int wn   = (wid & 3) << 5;
    int z          = blockIdx.z;
    const int m0   = blockIdx.y << 7;
    const int n0   = blockIdx.x << 7;

    const float*  Afz = Af0;
    const __half* Bz  = B0;
    float*        Cz  = C0;
    if (z >= z2)      { Afz = Af2; Bz = B2; Cz = C2; z -= z2; }
    else if (z >= z1) { Afz = Af1; Bz = B1; Cz = C1; z -= z1; }

    const float*  A  = AF32 ? (Afz + (long)z * sA + (long)m0 * lda) : nullptr;
    const __half* Ah = AF32 ? nullptr : (Ahg + (long)z * sA + (long)m0 * lda);
    const __half* B  = Bz + (long)z * sB + (long)n0 * ldb;
    float*        C  = Cz + (long)z * sC;

    const int nch  = K >> 5;
    const int lrow = tid >> 1, lhalf = tid & 1;
    const int soff = lrow * ROWB + lhalf * 32;

    float acc[4][4][4];
#pragma unroll
    for (int i = 0; i < 4; i++)
#pragma unroll
        for (int j = 0; j < 4; j++)
#pragma unroll
            for (int q = 0; q < 4; q++) acc[i][j][q] = 0.f;

    const uint32_t smbase = smem_u32(dsm);
    const int a_row  = wm + (lane & 15);
    const int a_koff = (lane >> 4) << 4;
    const int b_row  = wn + (lane & 7) + ((lane >> 4) & 1) * 8;
    const int b_koff = ((lane >> 3) & 1) << 4;

    const uint32_t cp_off  = (uint32_t)lrow * ROWB + (uint32_t)lhalf * 32;
    const long     cp_srcb = (long)lrow * ldb + lhalf * 16;
    const long     cp_srca = (long)lrow * lda + lhalf * 16;

    float ra[16];
    // ---- prologue: chunk 0 ----
    {
        CPA16(smbase + TILEB + cp_off,      B + cp_srcb);
        CPA16(smbase + TILEB + cp_off + 16, B + cp_srcb + 8);
        if (AF32) {
            const float4* pa = (const float4*)(A + (long)lrow * lda + lhalf * 16);
#pragma unroll
            for (int q = 0; q < 4; q++) *(float4*)(ra + 4 * q) = pa[q];
            uint32_t hw[8];
            cvt_hi16(ra, hw);
            *(uint4*)(dsm + soff)      = make_uint4(hw[0], hw[1], hw[2], hw[3]);
            *(uint4*)(dsm + soff + 16) = make_uint4(hw[4], hw[5], hw[6], hw[7]);
        } else {
            CPA16(smbase + cp_off,      Ah + cp_srca);
            CPA16(smbase + cp_off + 16, Ah + cp_srca + 8);
        }
        CPA_COMMIT();
        CPA_WAIT0();
    }
    __syncthreads();

    for (int i = 0; i < nch; i++) {
        // issue next chunk's loads before MMA
        if (i + 1 < nch) {
            const int k0 = (i + 1) << 5;
            const uint32_t bb = smbase + ((i + 1) & 1) * BUF1;
            CPA16(bb + TILEB + cp_off,      B + k0 + cp_srcb);
            CPA16(bb + TILEB + cp_off + 16, B + k0 + cp_srcb + 8);
            if (AF32) {
                const float4* pa = (const float4*)(A + (long)lrow * lda + k0 + lhalf * 16);
#pragma unroll
                for (int q = 0; q < 4; q++) *(float4*)(ra + 4 * q) = pa[q];
            } else {
                CPA16(bb + cp_off,      Ah + k0 + cp_srca);
                CPA16(bb + cp_off + 16, Ah + k0 + cp_srca + 8);
            }
            CPA_COMMIT();
        }
        // MMA on current buffer
        const uint32_t tb = smbase + (i & 1) * BUF1;
#pragma unroll
        for (int ks = 0; ks < 2; ks++) {
            uint32_t bh[4][2];
            const uint32_t ka = ks * 32 + a_koff;
            const uint32_t kb = ks * 32 + b_koff;
#pragma unroll
            for (int p = 0; p < 2; p++) {
                uint32_t r0, r1, r2, r3;
                LDSM4(r0, r1, r2, r3, tb + TILEB + (uint32_t)(b_row + p * 16) * ROWB + kb);
                bh[2 * p][0] = r0; bh[2 * p][1] = r1;
                bh[2 * p + 1][0] = r2; bh[2 * p + 1][1] = r3;
            }
#pragma unroll
            for (int mi = 0; mi < 4; mi++) {
                uint32_t ah[4];
                LDSM4(ah[0], ah[1], ah[2], ah[3],
                      tb + (uint32_t)(a_row + mi * 16) * ROWB + ka);
#pragma unroll
                for (int ni = 0; ni < 4; ni++) MMA16816(acc[mi][ni], ah, bh[ni]);
            }
        }
        // store next A chunk (fp32 path)
        if (i + 1 < nch) {
            if (AF32) {
                char* buf = dsm + ((i + 1) & 1) * BUF1;
                uint32_t hw[8];
                cvt_hi16(ra, hw);
                *(uint4*)(buf + soff)      = make_uint4(hw[0], hw[1], hw[2], hw[3]);
                *(uint4*)(buf + soff + 16) = make_uint4(hw[4], hw[5], hw[6], hw[7]);
            }
            CPA_WAIT0();
        }
        __syncthreads();
    }

    // epilogue
    const int g = lane >> 2, t = lane & 3;
#pragma unroll
    for (int mi = 0; mi < 4; mi++) {
        const int r0 = m0 + wm + mi * 16 + g;
#pragma unroll
        for (int ni = 0; ni < 4; ni++) {
            const int cc = n0 + wn + ni * 8 + t * 2;
            *(float2*)(C + (long)r0 * ldc + cc)       = make_float2(acc[mi][ni][0], acc[mi][ni][1]);
            *(float2*)(C + (long)(r0 + 8) * ldc + cc) = make_float2(acc[mi][ni][2], acc[mi][ni][3]);
        }
    }
}

// ================= flash attention: pure f16, 64 Q rows / CTA, 128 threads =================
// smem: QH [0,17408), K bufs [17408,+17408x2), VT bufs [52224,+18432x2)  total 89088
#define K_OFF  17408
#define KBUFB  17408
#define V_OFF  52224
#define VBUFB  18432
#define FSMEM  89088
#define FC     0.12751744f   // log2(e) / sqrt(128)

__device__ __forceinline__ void kv_prefetch(uint32_t smb, int buf, int kv0,
    const __half* __restrict__ khp, const __half* __restrict__ vhp, int tid)
{
#pragma unroll
    for (int i = 0; i < 8; i++) {
        int t = tid + (i << 7);
        int unit = t & 15, row = t >> 4;            // 0..63
        CPA16(smb + K_OFF + buf * KBUFB + row * 272 + unit * 16,
              khp + (long)(kv0 + row) * HD + unit * 8);
    }
#pragma unroll
    for (int i = 0; i < 8; i++) {
        int t = tid + (i << 7);
        int unit = t & 7, row = t >> 3;             // 0..127
        CPA16(smb + V_OFF + buf * VBUFB + row * 144 + unit * 16,
              vhp + (long)row * SEQ + kv0 + unit * 8);
    }
}

__global__ __launch_bounds__(128, 2)
void flash_k(const __half* __restrict__ qhg, const __half* __restrict__ khg,
             const __half* __restrict__ vhg, __half* __restrict__ oah)
{
    extern __shared__ char dsm[];
    const uint32_t smb = smem_u32(dsm);
    const int tid  = threadIdx.x;
    const int w    = tid >> 5;
    const int lane = tid & 31;
    const int z    = blockIdx.x;
    const int mb   = 31 - blockIdx.y;     // heavy blocks first
    const int kvh  = z >> 3;
    const int m0   = mb << 6;
    const int nt   = mb + 1;

    const __half* qhp = qhg + ((long)z * SEQ + m0) * HD;
    const __half* khp = khg + (long)kvh * SEQ * HD;
    const __half* vhp = vhg + (long)kvh * HD * SEQ;

    // Q -> smem (one-time): 64 rows x 8 16B-units
#pragma unroll
    for (int i = 0; i < 8; i++) {
        int t = tid + (i << 7);
        int unit = t & 15, row = t >> 4;
        CPA16(smb + row * 272 + unit * 16, qhp + (long)row * HD + unit * 8);
    }
    CPA_COMMIT();
    kv_prefetch(smb, 0, 0, khp, vhp, tid);
    CPA_COMMIT();

    // wait for Q (not necessarily kv0), then hoist Q fragments to registers
    CPA_WAIT1();
    __syncthreads();
    const uint32_t qa_h = smb + (uint32_t)((w << 4) + (lane & 15)) * 272 + ((lane >> 4) << 4);
    uint32_t qf[8][4];
#pragma unroll
    for (int j = 0; j < 8; j++)
        LDSM4(qf[j][0], qf[j][1], qf[j][2], qf[j][3], qa_h + j * 32);

    float o[16][4];
#pragma unroll
    for (int nb = 0; nb < 16; nb++)
#pragma unroll
        for (int q = 0; q < 4; q++) o[nb][q] = 0.f;
    float mr0 = -1e30f, mr1 = -1e30f, l0 = 0.f, l1 = 0.f;

    const int wrow = m0 + (w << 4);
    const uint32_t brow = (lane & 7) + ((lane >> 4) & 1) * 8;
    const uint32_t bko  = ((lane >> 3) & 1) << 4;

    int buf = 0;
    for (int it = 0; it < nt; it++) {
        if (it + 1 < nt) {
            kv_prefetch(smb, buf ^ 1, (it + 1) << 6, khp, vhp, tid);
            CPA_COMMIT();
            CPA_WAIT1();
        } else {
            CPA_WAIT0();
        }
        __syncthreads();

        const int kv0 = it << 6;
        {
            const uint32_t kb_h = smb + K_OFF + buf * KBUFB;
            const uint32_t vb_h = smb + V_OFF + buf * VBUFB;

            float s[8][4];
#pragma unroll
            for (int nb = 0; nb < 8; nb++)
#pragma unroll
                for (int q = 0; q < 4; q++) s[nb][q] = 0.f;

            // ---- scores: s = Q . K^T ----
#pragma unroll
            for (int j = 0; j < 8; j++) {
#pragma unroll
                for (int g16 = 0; g16 < 4; g16++) {
                    uint32_t bh[4];
                    const uint32_t ba = (uint32_t)(g16 * 16 + brow) * 272 + bko + j * 32;
                    LDSM4(bh[0], bh[1], bh[2], bh[3], kb_h + ba);
                    MMA16816(s[2 * g16],     qf[j], bh);
                    MMA16816(s[2 * g16 + 1], qf[j], bh + 2);
                }
            }

            // ---- causal mask ----
            const int r0 = wrow + (lane >> 2);
            const int c0 = kv0 + ((lane & 3) << 1);
            if (kv0 + 63 > wrow) {
#pragma unroll
                for (int nb = 0; nb < 8; nb++) {
                    const int c = c0 + nb * 8;
                    if (c     > r0    ) s[nb][0] = -1e30f;
                    if (c + 1 > r0    ) s[nb][1] = -1e30f;
                    if (c     > r0 + 8) s[nb][2] = -1e30f;
                    if (c + 1 > r0 + 8) s[nb][3] = -1e30f;
                }
            }

            // ---- online softmax ----
            float tm0 = -1e30f, tm1 = -1e30f;
#pragma unroll
            for (int nb = 0; nb < 8; nb++) {
                tm0 = fmaxf(tm0, fmaxf(s[nb][0], s[nb][1]));
                tm1 = fmaxf(tm1, fmaxf(s[nb][2], s[nb][3]));
            }
            tm0 = fmaxf(tm0, __shfl_xor_sync(0xffffffffu, tm0, 1));
            tm0 = fmaxf(tm0, __shfl_xor_sync(0xffffffffu, tm0, 2));
            tm1 = fmaxf(tm1, __shfl_xor_sync(0xffffffffu, tm1, 1));
            tm1 = fmaxf(tm1, __shfl_xor_sync(0xffffffffu, tm1, 2));
            const float mn0 = fmaxf(mr0, tm0), mn1 = fmaxf(mr1, tm1);
            const float sf0 = exp2f((mr0 - mn0) * FC);
            const float sf1 = exp2f((mr1 - mn1) * FC);
            mr0 = mn0; mr1 = mn1;
            l0 *= sf0;  l1 *= sf1;
#pragma unroll
            for (int nb = 0; nb < 16; nb++) {
                o[nb][0] *= sf0; o[nb][1] *= sf0;
                o[nb][2] *= sf1; o[nb][3] *= sf1;
            }
            float rs0 = 0.f, rs1 = 0.f;
#pragma unroll
            for (int nb = 0; nb < 8; nb++) {
                s[nb][0] = exp2f((s[nb][0] - mn0) * FC); rs0 += s[nb][0];
                s[nb][1] = exp2f((s[nb][1] - mn0) * FC); rs0 += s[nb][1];
                s[nb][2] = exp2f((s[nb][2] - mn1) * FC); rs1 += s[nb][2];
                s[nb][3] = exp2f((s[nb][3] - mn1) * FC); rs1 += s[nb][3];
            }
            rs0 += __shfl_xor_sync(0xffffffffu, rs0, 1);
            rs0 += __shfl_xor_sync(0xffffffffu, rs0, 2);
            rs1 += __shfl_xor_sync(0xffffffffu, rs1, 1);
            rs1 += __shfl_xor_sync(0xffffffffu, rs1, 2);
            l0 += rs0; l1 += rs1;

            // ---- PV: o += P . V ----
#pragma unroll
            for (int j = 0; j < 4; j++) {
                uint32_t pha[4];
#pragma unroll
                for (int hq = 0; hq < 4; hq++) {
                    const int nb = 2 * j + (hq >> 1);
                    const int e  = (hq & 1) << 1;
                    __half2 h = __floats2half2_rn(s[nb][e], s[nb][e + 1]);
                    pha[hq] = *reinterpret_cast<uint32_t*>(&h);
                }
#pragma unroll
                for (int g16 = 0; g16 < 8; g16++) {
                    uint32_t bh[4];
                    const uint32_t ba = (uint32_t)(g16 * 16 + brow) * 144 + bko + j * 32;
                    LDSM4(bh[0], bh[1], bh[2], bh[3], vb_h + ba);
                    MMA16816(o[2 * g16],     pha, bh);
                    MMA16816(o[2 * g16 + 1], pha, bh + 2);
                }
            }
        }
        __syncthreads();
        buf ^= 1;
    }

    // ---- epilogue: normalize, f16 ----
    const float inv0 = 1.f / l0, inv1 = 1.f / l1;
    const int r0 = wrow + (lane >> 2);
    const long base0 = ((long)z * SEQ + r0) * HD + ((lane & 3) << 1);
    const long base1 = base0 + 8 * HD;
#pragma unroll
    for (int nb = 0; nb < 16; nb++) {
        *(__half2*)(oah + base0 + nb * 8) =
            __floats2half2_rn(o[nb][0] * inv0, o[nb][1] * inv0);
        *(__half2*)(oah + base1 + nb * 8) =
            __floats2half2_rn(o[nb][2] * inv1, o[nb][3] * inv1);
    }
}

// ---------------- RoPE (merged q+k): fp32 in, f16 out ----------------
__global__ __launch_bounds__(256)
void rope_all(const float* __restrict__ qb, const float* __restrict__ kb,
              __half* __restrict__ qh, __half* __restrict__ kh,
              const int* __restrict__ pos)
{
    int idx = blockIdx.x * 256 + threadIdx.x;
    const int total = (NH + NKV) * SEQ * 64;
    if (idx >= total) return;
    int i = idx & 63;
    int l = (idx >> 6) % SEQ;
    int n = idx / (SEQ * 64);

    float invf = exp2f(-(float)i * 0.31143075889569023f);
    float ang  = (float)pos[l] * invf;
    float q  = rintf(ang * 0.15915494309189535f);
    float r  = ang - q * 6.28125f;
    r        = r   - q * 1.9353071795864769e-3f;
    float s, c;
    sincosf(r, &s, &c);

    const float* src;
    __half* dst;
    if (n < NH) { src = qb + ((long)n * SEQ + l) * HD;        dst = qh + ((long)n * SEQ + l) * HD; }
    else        { src = kb + ((long)(n - NH) * SEQ + l) * HD; dst = kh + ((long)(n - NH) * SEQ + l) * HD; }

    const float x1 = src[i], x2 = src[i + 64];
    dst[i]      = __float2half_rn(x1 * c - x2 * s);
    dst[i + 64] = __float2half_rn(x2 * c + x1 * s);
}

// ---------------- V transpose: fp32 [kv][S][128] -> f16 [kv][128][S] ----------------
__global__ __launch_bounds__(256)
void transpose_vh(const float* __restrict__ v, __half* __restrict__ vt)
{
    __shared__ float t[32][33];
    int h  = blockIdx.z;
    int s0 = blockIdx.x * 32, d0 = blockIdx.y * 32;
    const float* src = v + ((long)h * SEQ + s0) * HD + d0;
#pragma unroll
    for (int yy = threadIdx.y; yy < 32; yy += 8)
        t[yy][threadIdx.x] = src[yy * HD + threadIdx.x];
    __syncthreads();
    __half* dst = vt + ((long)h * HD + d0) * SEQ + s0;
#pragma unroll
    for (int yy = threadIdx.y; yy < 32; yy += 8)
        dst[(long)yy * SEQ + threadIdx.x] = __float2half_rn(t[threadIdx.x][yy]);
}

// ---------------- fp32 -> f16 all weights in one launch ----------------
__global__ __launch_bounds__(256)
void cvt16_all(const float* __restrict__ qw, const float* __restrict__ kw,
               const float* __restrict__ vw, const float* __restrict__ ow,
               __half* __restrict__ d)
{
    int e = (blockIdx.x * 256 + threadIdx.x) << 2;
    if (e >= W_TOT) return;
    const float* s;
    if      (e < KW_OFF) s = qw + e;
    else if (e < VW_OFF) s = kw + (e - KW_OFF);
    else if (e < OW_OFF) s = vw + (e - VW_OFF);
    else                 s = ow + (e - OW_OFF);
    float4 v = *(const float4*)s;
    ((__half2*)(d + e))[0] = __floats2half2_rn(v.x, v.y);
    ((__half2*)(d + e))[1] = __floats2half2_rn(v.z, v.w);
}

// ---------------- launch ----------------
extern "C" void kernel_launch(void* const* d_in, const int* in_sizes, int n_in,
                              void* d_out, int out_size)
{
    const float* qhid = (const float*)d_in[0];
    const float* khid = (const float*)d_in[1];
    const float* vhid = (const float*)d_in[2];
    const int*   pos  = (const int*)  d_in[4];
    const float* qw   = (const float*)d_in[5];
    const float* kw   = (const float*)d_in[6];
    const float* vw   = (const float*)d_in[7];
    const float* ow   = (const float*)d_in[8];
    float*       out  = (float*)d_out;

    float *qb, *kb, *vb;
    __half *qhh, *khh, *vth, *ahh, *wh;
    cudaGetSymbolAddress((void**)&qb,  g_q);
    cudaGetSymbolAddress((void**)&kb,  g_k);
    cudaGetSymbolAddress((void**)&vb,  g_v);
    cudaGetSymbolAddress((void**)&qhh, g_qh);
    cudaGetSymbolAddress((void**)&khh, g_kh);
    cudaGetSymbolAddress((void**)&vth, g_vth);
    cudaGetSymbolAddress((void**)&ahh, g_ah);
    cudaGetSymbolAddress((void**)&wh,  g_wh);

    cudaFuncSetAttribute(tgemm<true >, cudaFuncAttributeMaxDynamicSharedMemorySize, GSMB);
    cudaFuncSetAttribute(tgemm<false>, cudaFuncAttributeMaxDynamicSharedMemorySize, GSMB);
    cudaFuncSetAttribute(flash_k,      cudaFuncAttributeMaxDynamicSharedMemorySize, FSMEM);

    const long HH  = (long)SEQ * HIDDEN;
    const long HDW = (long)HD * HIDDEN;
    const long SH  = (long)SEQ * HD;

    // all weights -> f16 (single launch)
    cvt16_all<<<(W_TOT / 4 + 255) / 256, 256>>>(qw, kw, vw, ow, wh);

    // Q+K+V projections merged into ONE launch (z: 0-15 Q, 16-17 K, 18-19 V)
    tgemm<true><<<dim3(1, 16, NH + 2 * NKV), 256, GSMB>>>(
        qhid, nullptr, wh + QW_OFF, qb,
        khid, wh + KW_OFF, kb,
        vhid, wh + VW_OFF, vb,
        NH, NH + NKV,
        HIDDEN, HIDDEN, HIDDEN, HD, HH, HDW, SH);

    // RoPE q+k merged -> f16
    rope_all<<<((NH + NKV) * SEQ * 64 + 255) / 256, 256>>>(qb, kb, qhh, khh, pos);

    // V transpose -> f16
    transpose_vh<<<dim3(64, 4, NKV), dim3(32, 8)>>>(vb, vth);

    // fused attention -> attn f16
    flash_k<<<dim3(NH, 32), 128, FSMEM>>>(qhh, khh, vth, ahh);

    // O projection: A = attn f16, B = ow f16 (per-head offset z*128)
    tgemm<false><<<dim3(16, 16, NH), 256, GSMB>>>(
        nullptr, ahh, wh + OW_OFF, out,
        nullptr, nullptr, nullptr,
        nullptr, nullptr, nullptr, 99, 99,
        HD, HD, HIDDEN, HIDDEN, SH, (long)HD, HH);
}